// round 10
// baseline (speedup 1.0000x reference)
#include <cuda_runtime.h>
#include <cuda_bf16.h>
#include <cstdint>
#include <math.h>

typedef unsigned int u32;
typedef unsigned long long u64;

#define BATCH 4
#define NPTS 4995
#define CDIM 128
#define KNN 10
#define IMG 224
#define IMGSZ (IMG*IMG)

#define MT 128
#define MTILES 40
#define NSPLIT 4
#define CHUNK 1280
#define K2_THREADS 512

// K2 smem layout (bytes)
#define BBUF 34816          // one 64-row B buffer: hi 17408 + lo 17408
#define BLO 17408
#define AH_SM 0
#define AL_SM 34816
#define BB_SM 69632         // 4 buffers x 34816 = 139264
#define CI_SM 208896        // 4 x 1024
#define MG_SM 212992        // 128 x 5 floats
#define K2SMEM 215552

#define K3CH 2048
#define K4HALF 2498

// ---------------- scratch ----------------
__device__ unsigned short g_f1hi[BATCH*NPTS*CDIM];
__device__ unsigned short g_f1lo[BATCH*NPTS*CDIM];
__device__ unsigned short g_f2hi[BATCH*NPTS*CDIM];
__device__ unsigned short g_f2lo[BATCH*NPTS*CDIM];
__device__ float g_nf1[BATCH*NPTS];
__device__ float g_nf2[BATCH*NPTS];
__device__ float g_pm[BATCH*NPTS*NSPLIT];
__device__ float g_ps[BATCH*NPTS*NSPLIT];
__device__ float g_px[BATCH*NPTS*NSPLIT];
__device__ float g_py[BATCH*NPTS*NSPLIT];
__device__ float g_pz[BATCH*NPTS*NSPLIT];
__device__ float g_verts12[BATCH*NPTS*3];
__device__ int   g_idx11[BATCH*NPTS*KNN];
__device__ float g_k4v[BATCH*NPTS*20];
__device__ int   g_k4i[BATCH*NPTS*20];
__device__ float g_img[2][BATCH*IMGSZ];
__device__ unsigned g_pminE[2][BATCH][2];
__device__ unsigned g_pmaxE[2][BATCH][2];
__device__ int g_iminI[2][BATCH][2];
__device__ int g_imaxI[2][BATCH][2];
__device__ double g_self_sum;
__device__ double g_deform_sum;
__device__ double g_img_sum;

// ---------------- generic helpers ----------------
__device__ __forceinline__ unsigned fenc(float f){
    unsigned uu = __float_as_uint(f);
    return (uu & 0x80000000u) ? ~uu : (uu | 0x80000000u);
}
__device__ __forceinline__ float fdec(unsigned uu){
    return __uint_as_float((uu & 0x80000000u) ? (uu ^ 0x80000000u) : ~uu);
}
__device__ __forceinline__ float sqrt_approx(float x){
    float y; asm("sqrt.approx.f32 %0, %1;" : "=f"(y) : "f"(x)); return y;
}
__device__ __forceinline__ void block_sum_atomic(float v, double* target){
    __shared__ float red[32];
    int lane = threadIdx.x & 31, w = threadIdx.x >> 5;
    #pragma unroll
    for (int o = 16; o; o >>= 1) v += __shfl_xor_sync(0xffffffffu, v, o);
    if (!lane) red[w] = v;
    __syncthreads();
    if (w == 0){
        int nw = (blockDim.x + 31) >> 5;
        float s = (lane < nw) ? red[lane] : 0.f;
        #pragma unroll
        for (int o = 16; o; o >>= 1) s += __shfl_xor_sync(0xffffffffu, s, o);
        if (!lane) atomicAdd(target, (double)s);
    }
}
__device__ __forceinline__ u32 smem_u32(const void* p){
    u32 a;
    asm("{ .reg .u64 t; cvta.to.shared.u64 t, %1; cvt.u32.u64 %0, t; }" : "=r"(a) : "l"(p));
    return a;
}
__device__ __forceinline__ void bar_named(int id){
    asm volatile("bar.sync %0, 256;" :: "r"(id) : "memory");
}

// ---------------- mma.sync / ldmatrix wrappers ----------------
__device__ __forceinline__ void ldsm_x4(u32* r, u32 addr){
    asm volatile("ldmatrix.sync.aligned.m8n8.x4.shared.b16 {%0,%1,%2,%3}, [%4];"
        : "=r"(r[0]), "=r"(r[1]), "=r"(r[2]), "=r"(r[3]) : "r"(addr));
}
__device__ __forceinline__ void mma_bf16(float* d, const u32* a, u32 b0, u32 b1){
    asm volatile(
        "mma.sync.aligned.m16n8k16.row.col.f32.bf16.bf16.f32 "
        "{%0,%1,%2,%3}, {%4,%5,%6,%7}, {%8,%9}, {%0,%1,%2,%3};"
        : "+f"(d[0]), "+f"(d[1]), "+f"(d[2]), "+f"(d[3])
        : "r"(a[0]), "r"(a[1]), "r"(a[2]), "r"(a[3]), "r"(b0), "r"(b1));
}

// ---------------- K0: init ----------------
__global__ void k_init(){
    int i = blockIdx.x*blockDim.x + threadIdx.x;
    if (i < 2*BATCH*IMGSZ) ((float*)g_img)[i] = 0.0f;
    if (i == 0){ g_self_sum = 0.0; g_deform_sum = 0.0; g_img_sum = 0.0; }
    if (i < 16){
        ((unsigned*)g_pminE)[i] = 0xFFFFFFFFu;
        ((unsigned*)g_pmaxE)[i] = 0u;
        ((int*)g_iminI)[i] = 0x7FFFFFFF;
        ((int*)g_imaxI)[i] = (int)0x80000000;
    }
}

// ---------------- Kprep: double-bf16 split ----------------
__global__ void __launch_bounds__(256) kprep(const float* __restrict__ f1,
                                             const float* __restrict__ f2){
    const int half = BATCH*NPTS*CDIM/4;
    int i = blockIdx.x*256 + threadIdx.x;
    if (i >= 2*half) return;
    bool second = i >= half;
    int j = second ? i - half : i;
    float4 v = ((const float4*)(second ? f2 : f1))[j];
    unsigned short* hi = second ? g_f2hi : g_f1hi;
    unsigned short* lo = second ? g_f2lo : g_f1lo;
    float vv[4]; vv[0]=v.x; vv[1]=v.y; vv[2]=v.z; vv[3]=v.w;
    unsigned short hu[4], lu[4];
    #pragma unroll
    for (int c = 0; c < 4; c++){
        __nv_bfloat16 h = __float2bfloat16_rn(vv[c]);
        float r = vv[c] - __bfloat162float(h);
        __nv_bfloat16 l = __float2bfloat16_rn(r);
        hu[c] = __bfloat16_as_ushort(h);
        lu[c] = __bfloat16_as_ushort(l);
    }
    ((uint2*)hi)[j] = make_uint2((u32)hu[0] | ((u32)hu[1] << 16),
                                 (u32)hu[2] | ((u32)hu[3] << 16));
    ((uint2*)lo)[j] = make_uint2((u32)lu[0] | ((u32)lu[1] << 16),
                                 (u32)lu[2] | ((u32)lu[3] << 16));
}

// ---------------- K1: feature row norms ----------------
__global__ void __launch_bounds__(256) k1_norms(const float* __restrict__ f1,
                                                const float* __restrict__ f2){
    int gw = (blockIdx.x*blockDim.x + threadIdx.x) >> 5;
    int lane = threadIdx.x & 31;
    if (gw >= 2*BATCH*NPTS) return;
    const float* src; float* dst; int row;
    if (gw < BATCH*NPTS){ src = f1; dst = g_nf1; row = gw; }
    else { src = f2; dst = g_nf2; row = gw - BATCH*NPTS; }
    float4 v = *(const float4*)(src + (size_t)row*CDIM + lane*4);
    float s = v.x*v.x + v.y*v.y + v.z*v.z + v.w*v.w;
    #pragma unroll
    for (int o = 16; o; o >>= 1) s += __shfl_xor_sync(0xffffffffu, s, o);
    if (!lane) dst[row] = s;
}

// ---------------- K2: HMMA fused softmax, two warp-groups pipelined ----------------
__global__ void __launch_bounds__(K2_THREADS)
k2_softmax_mma(const float* __restrict__ verts2){
    extern __shared__ char smem[];
    const int tid = threadIdx.x;
    const int wid = tid >> 5, lane = tid & 31;
    const int grp = wid >> 3;         // 0 or 1
    const int gwid = wid & 7;         // warp within group: 16-row slice
    const int gtid = tid & 255;       // thread within group
    const int b = blockIdx.z, split = blockIdx.y, mt = blockIdx.x;
    const int n0 = mt * MT;
    const int cs = split * CHUNK;
    const int ce = min(cs + CHUNK, NPTS);
    const int T = (ce - cs + 63) >> 6;      // 64-wide tiles
    const int H = (T + 1) >> 1;
    const int tbase = grp ? H : 0;
    const int myT = grp ? (T - H) : H;
    const size_t bofs = (size_t)b * NPTS;
    const float* v2 = verts2 + bofs * 3;
    u32 sb = smem_u32(smem);

    // stage A tile (hi & lo), all 512 threads
    for (int i = tid; i < 2048; i += K2_THREADS){
        int row = i >> 4, c8 = i & 15;
        int n = n0 + row;
        uint4 vh = make_uint4(0u,0u,0u,0u);
        uint4 vl = make_uint4(0u,0u,0u,0u);
        if (n < NPTS){
            vh = *(const uint4*)(g_f1hi + ((bofs + n) << 7) + (c8 << 3));
            vl = *(const uint4*)(g_f1lo + ((bofs + n) << 7) + (c8 << 3));
        }
        *(uint4*)(smem + AH_SM + row*272 + c8*16) = vh;
        *(uint4*)(smem + AL_SM + row*272 + c8*16) = vl;
    }
    // each group stages its first B tile (64 rows) + colinfo
    if (myT > 0){
        int m0 = cs + tbase*64;
        char* bufb = smem + BB_SM + (grp*2 + 0)*BBUF;
        for (int i = gtid; i < 2048; i += 256){
            int row = i >> 5, c8 = i & 31;
            int m = m0 + row;
            uint4 v = make_uint4(0u,0u,0u,0u);
            const unsigned short* src = (c8 < 16) ? g_f2hi : g_f2lo;
            int cc8 = c8 & 15;
            if (m < ce) v = *(const uint4*)(src + ((bofs + m) << 7) + (cc8 << 3));
            *(uint4*)(bufb + ((c8 < 16) ? 0 : BLO) + row*272 + cc8*16) = v;
        }
        if (gtid < 64){
            int m = m0 + gtid;
            float4 ci;
            if (m < ce){ ci.x = g_nf2[bofs+m]; ci.y = v2[m*3]; ci.z = v2[m*3+1]; ci.w = v2[m*3+2]; }
            else { ci.x = 1e30f; ci.y = 0.f; ci.z = 0.f; ci.w = 0.f; }
            *(float4*)(smem + CI_SM + (grp*2 + 0)*1024 + gtid*16) = ci;
        }
    }
    __syncthreads();

    const u32 aRowOff = (u32)((gwid*16 + (lane & 15)) * 272 + (lane >> 4) * 16);
    const u32 aHa = sb + AH_SM + aRowOff;
    const u32 aLa = sb + AL_SM + aRowOff;
    const u32 bOff4 = (u32)(((lane & 7) + ((lane >> 4) << 3)) * 272 + (((lane >> 3) & 1) << 4));

    float nf10 = 0.f, nf11 = 0.f;
    const int r0g = n0 + gwid*16 + (lane >> 2);
    if (r0g < NPTS) nf10 = g_nf1[bofs + r0g];
    if (r0g + 8 < NPTS) nf11 = g_nf1[bofs + r0g + 8];

    float rm0=-1e30f, rs0=0.f, rx0=0.f, ry0=0.f, rz0=0.f;
    float rm1=-1e30f, rs1=0.f, rx1=0.f, ry1=0.f, rz1=0.f;

    for (int j = 0; j < myT; j++){
        // prefetch next tile of this group
        if (j + 1 < myT){
            int m0 = cs + (tbase + j + 1)*64;
            int nb = (j + 1) & 1;
            char* bufb = smem + BB_SM + (grp*2 + nb)*BBUF;
            for (int i = gtid; i < 2048; i += 256){
                int row = i >> 5, c8 = i & 31;
                int m = m0 + row;
                uint4 v = make_uint4(0u,0u,0u,0u);
                const unsigned short* src = (c8 < 16) ? g_f2hi : g_f2lo;
                int cc8 = c8 & 15;
                if (m < ce) v = *(const uint4*)(src + ((bofs + m) << 7) + (cc8 << 3));
                *(uint4*)(bufb + ((c8 < 16) ? 0 : BLO) + row*272 + cc8*16) = v;
            }
            if (gtid < 64){
                int m = m0 + gtid;
                float4 ci;
                if (m < ce){ ci.x = g_nf2[bofs+m]; ci.y = v2[m*3]; ci.z = v2[m*3+1]; ci.w = v2[m*3+2]; }
                else { ci.x = 1e30f; ci.y = 0.f; ci.z = 0.f; ci.w = 0.f; }
                *(float4*)(smem + CI_SM + (grp*2 + nb)*1024 + gtid*16) = ci;
            }
        }

        // MMA on current buffer
        float acc[32];
        #pragma unroll
        for (int i = 0; i < 32; i++) acc[i] = 0.f;
        const u32 bBase = sb + BB_SM + (u32)((grp*2 + (j & 1))*BBUF) + bOff4;
        #pragma unroll
        for (int ks = 0; ks < 8; ks++){
            u32 ah[4], al[4];
            ldsm_x4(ah, aHa + ks*32);
            ldsm_x4(al, aLa + ks*32);
            #pragma unroll
            for (int fp = 0; fp < 4; fp++){
                u32 bh[4], bl[4];
                u32 baddr = bBase + (u32)(fp*4352 + ks*32);
                ldsm_x4(bh, baddr);
                ldsm_x4(bl, baddr + BLO);
                mma_bf16(acc + fp*8,     ah, bh[0], bh[1]);
                mma_bf16(acc + fp*8,     ah, bl[0], bl[1]);
                mma_bf16(acc + fp*8,     al, bh[0], bh[1]);
                mma_bf16(acc + fp*8 + 4, ah, bh[2], bh[3]);
                mma_bf16(acc + fp*8 + 4, ah, bl[2], bl[3]);
                mma_bf16(acc + fp*8 + 4, al, bh[2], bh[3]);
            }
        }

        // online softmax epilogue
        const char* cib = smem + CI_SM + (grp*2 + (j & 1))*1024;
        float tm0 = -1e30f, tm1 = -1e30f;
        #pragma unroll
        for (int f = 0; f < 8; f++){
            int n = f*8 + (lane & 3)*2;
            float c0x = *(const float*)(cib + n*16);
            float c1x = *(const float*)(cib + n*16 + 16);
            float s0 = fmaxf(fmaf(-2.f, acc[f*4+0], nf10 + c0x), 1e-12f);
            float s1 = fmaxf(fmaf(-2.f, acc[f*4+1], nf10 + c1x), 1e-12f);
            float s2 = fmaxf(fmaf(-2.f, acc[f*4+2], nf11 + c0x), 1e-12f);
            float s3 = fmaxf(fmaf(-2.f, acc[f*4+3], nf11 + c1x), 1e-12f);
            acc[f*4+0] = -100.f*sqrt_approx(s0);
            acc[f*4+1] = -100.f*sqrt_approx(s1);
            acc[f*4+2] = -100.f*sqrt_approx(s2);
            acc[f*4+3] = -100.f*sqrt_approx(s3);
            tm0 = fmaxf(tm0, fmaxf(acc[f*4+0], acc[f*4+1]));
            tm1 = fmaxf(tm1, fmaxf(acc[f*4+2], acc[f*4+3]));
        }
        float nm0 = fmaxf(rm0, tm0), nm1 = fmaxf(rm1, tm1);
        float sc0 = __expf(rm0 - nm0), sc1 = __expf(rm1 - nm1);
        rs0 *= sc0; rx0 *= sc0; ry0 *= sc0; rz0 *= sc0; rm0 = nm0;
        rs1 *= sc1; rx1 *= sc1; ry1 *= sc1; rz1 *= sc1; rm1 = nm1;
        #pragma unroll
        for (int f = 0; f < 8; f++){
            int n = f*8 + (lane & 3)*2;
            float4 c0 = *(const float4*)(cib + n*16);
            float4 c1 = *(const float4*)(cib + n*16 + 16);
            float w0 = __expf(acc[f*4+0] - nm0);
            float w1 = __expf(acc[f*4+1] - nm0);
            float w2 = __expf(acc[f*4+2] - nm1);
            float w3 = __expf(acc[f*4+3] - nm1);
            rs0 += w0 + w1; rs1 += w2 + w3;
            rx0 = fmaf(w0, c0.y, fmaf(w1, c1.y, rx0));
            ry0 = fmaf(w0, c0.z, fmaf(w1, c1.z, ry0));
            rz0 = fmaf(w0, c0.w, fmaf(w1, c1.w, rz0));
            rx1 = fmaf(w2, c0.y, fmaf(w3, c1.y, rx1));
            ry1 = fmaf(w2, c0.z, fmaf(w3, c1.z, ry1));
            rz1 = fmaf(w2, c0.w, fmaf(w3, c1.w, rz1));
        }
        bar_named(1 + grp);
    }

    // merge across the 4 lanes of each row quad (warp covers all 64 cols of its tiles)
    #pragma unroll
    for (int o = 1; o <= 2; o <<= 1){
        float om = __shfl_xor_sync(0xffffffffu, rm0, o);
        float os = __shfl_xor_sync(0xffffffffu, rs0, o);
        float ox = __shfl_xor_sync(0xffffffffu, rx0, o);
        float oy = __shfl_xor_sync(0xffffffffu, ry0, o);
        float oz = __shfl_xor_sync(0xffffffffu, rz0, o);
        float nm = fmaxf(rm0, om);
        float e1 = __expf(rm0 - nm), e2 = __expf(om - nm);
        rs0 = rs0*e1 + os*e2; rx0 = rx0*e1 + ox*e2;
        ry0 = ry0*e1 + oy*e2; rz0 = rz0*e1 + oz*e2; rm0 = nm;
        om = __shfl_xor_sync(0xffffffffu, rm1, o);
        os = __shfl_xor_sync(0xffffffffu, rs1, o);
        ox = __shfl_xor_sync(0xffffffffu, rx1, o);
        oy = __shfl_xor_sync(0xffffffffu, ry1, o);
        oz = __shfl_xor_sync(0xffffffffu, rz1, o);
        nm = fmaxf(rm1, om);
        e1 = __expf(rm1 - nm); e2 = __expf(om - nm);
        rs1 = rs1*e1 + os*e2; rx1 = rx1*e1 + ox*e2;
        ry1 = ry1*e1 + oy*e2; rz1 = rz1*e1 + oz*e2; rm1 = nm;
    }

    // cross-group merge through smem
    __syncthreads();
    float* mg = (float*)(smem + MG_SM);
    int rl0 = gwid*16 + (lane >> 2);
    if (grp == 1 && (lane & 3) == 0){
        mg[rl0*5+0] = rm0; mg[rl0*5+1] = rs0; mg[rl0*5+2] = rx0; mg[rl0*5+3] = ry0; mg[rl0*5+4] = rz0;
        mg[(rl0+8)*5+0] = rm1; mg[(rl0+8)*5+1] = rs1; mg[(rl0+8)*5+2] = rx1; mg[(rl0+8)*5+3] = ry1; mg[(rl0+8)*5+4] = rz1;
    }
    __syncthreads();
    if (grp == 0 && (lane & 3) == 0){
        float m2 = mg[rl0*5+0], s2 = mg[rl0*5+1], x2 = mg[rl0*5+2], y2 = mg[rl0*5+3], z2 = mg[rl0*5+4];
        float nm = fmaxf(rm0, m2);
        float e1 = __expf(rm0 - nm), e2 = __expf(m2 - nm);
        float S = rs0*e1 + s2*e2, X = rx0*e1 + x2*e2, Y = ry0*e1 + y2*e2, Z = rz0*e1 + z2*e2;
        int n = n0 + rl0;
        if (n < NPTS){
            size_t pi = (bofs + n)*NSPLIT + split;
            g_pm[pi] = nm; g_ps[pi] = S; g_px[pi] = X; g_py[pi] = Y; g_pz[pi] = Z;
        }
        m2 = mg[(rl0+8)*5+0]; s2 = mg[(rl0+8)*5+1]; x2 = mg[(rl0+8)*5+2]; y2 = mg[(rl0+8)*5+3]; z2 = mg[(rl0+8)*5+4];
        nm = fmaxf(rm1, m2);
        e1 = __expf(rm1 - nm); e2 = __expf(m2 - nm);
        S = rs1*e1 + s2*e2; X = rx1*e1 + x2*e2; Y = ry1*e1 + y2*e2; Z = rz1*e1 + z2*e2;
        n = n0 + rl0 + 8;
        if (n < NPTS){
            size_t pi = (bofs + n)*NSPLIT + split;
            g_pm[pi] = nm; g_ps[pi] = S; g_px[pi] = X; g_py[pi] = Y; g_pz[pi] = Z;
        }
    }
}

// ---------------- K2b: merge splits -> verts12 ----------------
__global__ void __launch_bounds__(256) k2b_merge(){
    int i = blockIdx.x*256 + threadIdx.x;
    if (i >= BATCH*NPTS) return;
    float m = -1e30f, s = 0.f, x = 0.f, y = 0.f, z = 0.f;
    #pragma unroll
    for (int sp = 0; sp < NSPLIT; sp++){
        size_t pi = (size_t)i*NSPLIT + sp;
        float m2 = g_pm[pi], s2 = g_ps[pi], x2 = g_px[pi], y2 = g_py[pi], z2 = g_pz[pi];
        float nm = fmaxf(m, m2);
        float a1 = __expf(m - nm), a2 = __expf(m2 - nm);
        s = s*a1 + s2*a2; x = x*a1 + x2*a2; y = y*a1 + y2*a2; z = z*a1 + z2*a2;
        m = nm;
    }
    float inv = 1.f / s;
    g_verts12[(size_t)i*3 + 0] = x*inv;
    g_verts12[(size_t)i*3 + 1] = y*inv;
    g_verts12[(size_t)i*3 + 2] = z*inv;
}

// ---------------- K3: self_rec ----------------
__global__ void __launch_bounds__(256) k3_selfrec(const float* __restrict__ verts2){
    __shared__ __align__(16) float sx[K3CH+4];
    __shared__ __align__(16) float sy[K3CH+4];
    __shared__ __align__(16) float sz[K3CH+4];
    int b = blockIdx.y;
    int part = threadIdx.x & 3;
    int nl = threadIdx.x >> 2;
    int n = blockIdx.x*64 + nl;
    bool valid = n < NPTS;
    float vx=0.f, vy=0.f, vz=0.f;
    if (valid){
        vx = g_verts12[((size_t)b*NPTS + n)*3 + 0];
        vy = g_verts12[((size_t)b*NPTS + n)*3 + 1];
        vz = g_verts12[((size_t)b*NPTS + n)*3 + 2];
    }
    const float* v2 = verts2 + (size_t)b*NPTS*3;
    float best = 3.4e38f;
    for (int m0 = 0; m0 < NPTS; m0 += K3CH){
        int cnt = min(K3CH, NPTS - m0);
        __syncthreads();
        for (int i = threadIdx.x; i < cnt; i += 256){
            sx[i] = v2[(m0+i)*3]; sy[i] = v2[(m0+i)*3+1]; sz[i] = v2[(m0+i)*3+2];
        }
        if (threadIdx.x < 4){
            sx[cnt+threadIdx.x] = 1e30f; sy[cnt+threadIdx.x] = 1e30f; sz[cnt+threadIdx.x] = 1e30f;
        }
        __syncthreads();
        int ng = (cnt + 3) >> 2;
        for (int g = part; g < ng; g += 4){
            float4 X = *(const float4*)(sx + 4*g);
            float4 Y = *(const float4*)(sy + 4*g);
            float4 Z = *(const float4*)(sz + 4*g);
            float dx0 = vx-X.x, dy0 = vy-Y.x, dz0 = vz-Z.x;
            float dx1 = vx-X.y, dy1 = vy-Y.y, dz1 = vz-Z.y;
            float dx2 = vx-X.z, dy2 = vy-Y.z, dz2 = vz-Z.z;
            float dx3 = vx-X.w, dy3 = vy-Y.w, dz3 = vz-Z.w;
            float d0 = fmaf(dx0,dx0, fmaf(dy0,dy0, dz0*dz0));
            float d1 = fmaf(dx1,dx1, fmaf(dy1,dy1, dz1*dz1));
            float d2 = fmaf(dx2,dx2, fmaf(dy2,dy2, dz2*dz2));
            float d3 = fmaf(dx3,dx3, fmaf(dy3,dy3, dz3*dz3));
            best = fminf(best, fminf(fminf(d0,d1), fminf(d2,d3)));
        }
    }
    best = fminf(best, __shfl_xor_sync(0xffffffffu, best, 1));
    best = fminf(best, __shfl_xor_sync(0xffffffffu, best, 2));
    float contrib = (part == 0 && valid) ? best : 0.f;
    __syncthreads();
    block_sum_atomic(contrib, &g_self_sum);
}

// ---------------- K4: top-10 (candidate-split halves) ----------------
__global__ void __launch_bounds__(256) k4_topk(const float* __restrict__ verts1){
    __shared__ __align__(16) float sx[K3CH+4];
    __shared__ __align__(16) float sy[K3CH+4];
    __shared__ __align__(16) float sz[K3CH+4];
    __shared__ float smval[256][10];
    __shared__ int   smidx[256][10];
    int b = blockIdx.y;
    int h = blockIdx.z;
    int cstart = h*K4HALF;
    int cend = min(NPTS, cstart + K4HALF);
    int part = threadIdx.x & 3;
    int nl = threadIdx.x >> 2;
    int n = blockIdx.x*64 + nl;
    const float* v1 = verts1 + (size_t)b*NPTS*3;
    float vx=0.f, vy=0.f, vz=0.f;
    if (n < NPTS){ vx = v1[3*n]; vy = v1[3*n+1]; vz = v1[3*n+2]; }
    float val[10]; int idx[10];
    #pragma unroll
    for (int q = 0; q < 10; q++){ val[q] = 3.4e38f; idx[q] = 0; }
    for (int m0 = cstart; m0 < cend; m0 += K3CH){
        int cnt = min(K3CH, cend - m0);
        __syncthreads();
        for (int i = threadIdx.x; i < cnt; i += 256){
            sx[i] = v1[(m0+i)*3]; sy[i] = v1[(m0+i)*3+1]; sz[i] = v1[(m0+i)*3+2];
        }
        if (threadIdx.x < 4){
            sx[cnt+threadIdx.x] = 1e30f; sy[cnt+threadIdx.x] = 1e30f; sz[cnt+threadIdx.x] = 1e30f;
        }
        __syncthreads();
        int ng = (cnt + 3) >> 2;
        for (int g = part; g < ng; g += 4){
            float4 X = *(const float4*)(sx + 4*g);
            float4 Y = *(const float4*)(sy + 4*g);
            float4 Z = *(const float4*)(sz + 4*g);
            float dx0 = vx-X.x, dy0 = vy-Y.x, dz0 = vz-Z.x;
            float dx1 = vx-X.y, dy1 = vy-Y.y, dz1 = vz-Z.y;
            float dx2 = vx-X.z, dy2 = vy-Y.z, dz2 = vz-Z.z;
            float dx3 = vx-X.w, dy3 = vy-Y.w, dz3 = vz-Z.w;
            float d0 = fmaf(dx0,dx0, fmaf(dy0,dy0, dz0*dz0));
            float d1 = fmaf(dx1,dx1, fmaf(dy1,dy1, dz1*dz1));
            float d2 = fmaf(dx2,dx2, fmaf(dy2,dy2, dz2*dz2));
            float d3 = fmaf(dx3,dx3, fmaf(dy3,dy3, dz3*dz3));
            float gm = fminf(fminf(d0,d1), fminf(d2,d3));
            if (gm < val[9]){
                float ds[4]; ds[0]=d0; ds[1]=d1; ds[2]=d2; ds[3]=d3;
                #pragma unroll
                for (int k = 0; k < 4; k++){
                    if (ds[k] < val[9]){
                        float cv = ds[k]; int ci = m0 + 4*g + k;
                        #pragma unroll
                        for (int q = 0; q < 10; q++){
                            if (cv < val[q]){
                                float tv = val[q]; int ti = idx[q];
                                val[q] = cv; idx[q] = ci; cv = tv; ci = ti;
                            }
                        }
                    }
                }
            }
        }
    }
    #pragma unroll
    for (int q = 0; q < 10; q++){ smval[threadIdx.x][q] = val[q]; smidx[threadIdx.x][q] = idx[q]; }
    __syncthreads();
    if (part == 0 && n < NPTS){
        int h0=0,h1=0,h2=0,h3=0;
        int base = threadIdx.x;
        int out = (b*NPTS + n)*20 + h*10;
        #pragma unroll
        for (int q = 0; q < 10; q++){
            float b0 = smval[base][h0],   b1 = smval[base+1][h1];
            float b2 = smval[base+2][h2], b3 = smval[base+3][h3];
            float mm = fminf(fminf(b0,b1), fminf(b2,b3));
            float cv; int chosen;
            if (mm == b0){ cv = b0; chosen = smidx[base][h0];   h0++; }
            else if (mm == b1){ cv = b1; chosen = smidx[base+1][h1]; h1++; }
            else if (mm == b2){ cv = b2; chosen = smidx[base+2][h2]; h2++; }
            else { cv = b3; chosen = smidx[base+3][h3]; h3++; }
            g_k4v[out + q] = cv;
            g_k4i[out + q] = chosen;
        }
    }
}

// ---------------- K4b: merge two sorted top-10 halves ----------------
__global__ void __launch_bounds__(256) k4b_merge(){
    int i = blockIdx.x*256 + threadIdx.x;
    if (i >= BATCH*NPTS) return;
    int base = i*20;
    int p0 = 0, p1 = 0;
    #pragma unroll
    for (int q = 0; q < 10; q++){
        float v0 = g_k4v[base + p0];
        float v1 = g_k4v[base + 10 + p1];
        int chosen;
        if (v0 <= v1){ chosen = g_k4i[base + p0]; p0++; }
        else { chosen = g_k4i[base + 10 + p1]; p1++; }
        g_idx11[i*KNN + q] = chosen;
    }
}

// ---------------- K5: deform feature MSE (warp-per-point) ----------------
__global__ void __launch_bounds__(256) k5_deform(const float* __restrict__ feat1){
    int w = threadIdx.x >> 5, lane = threadIdx.x & 31;
    int base = blockIdx.x*64 + w*8;
    float acc = 0.f;
    #pragma unroll
    for (int p = 0; p < 8; p++){
        int bn = base + p;
        if (bn < BATCH*NPTS){
            int b = bn / NPTS, n = bn - b*NPTS;
            const float* f1 = feat1 + (size_t)b*NPTS*CDIM;
            float4 fc = *(const float4*)(f1 + (size_t)n*CDIM + lane*4);
            #pragma unroll
            for (int q = 0; q < KNN; q++){
                int m = g_idx11[bn*KNN + q];
                float4 fm = *(const float4*)(f1 + (size_t)m*CDIM + lane*4);
                float d0 = fm.x - fc.x, d1 = fm.y - fc.y;
                float d2 = fm.z - fc.z, d3 = fm.w - fc.w;
                acc = fmaf(d0,d0, acc); acc = fmaf(d1,d1, acc);
                acc = fmaf(d2,d2, acc); acc = fmaf(d3,d3, acc);
            }
        }
    }
    block_sum_atomic(acc, &g_deform_sum);
}

// ---------------- K6: per-batch xy min/max ----------------
__global__ void __launch_bounds__(256) k6_ptminmax(const float* __restrict__ verts2){
    __shared__ float r0[8], r1[8], r2[8], r3[8];
    int tb = blockIdx.y;
    int tensor = tb >> 2, b = tb & 3;
    const float* p = tensor ? (verts2 + (size_t)b*NPTS*3) : (g_verts12 + (size_t)b*NPTS*3);
    int i = blockIdx.x*256 + threadIdx.x;
    float mnx = 1e30f, mny = 1e30f, mxx = -1e30f, mxy = -1e30f;
    if (i < NPTS){ mnx = mxx = p[3*i]; mny = mxy = p[3*i+1]; }
    int lane = threadIdx.x & 31, w = threadIdx.x >> 5;
    #pragma unroll
    for (int o = 16; o; o >>= 1){
        mnx = fminf(mnx, __shfl_xor_sync(0xffffffffu, mnx, o));
        mny = fminf(mny, __shfl_xor_sync(0xffffffffu, mny, o));
        mxx = fmaxf(mxx, __shfl_xor_sync(0xffffffffu, mxx, o));
        mxy = fmaxf(mxy, __shfl_xor_sync(0xffffffffu, mxy, o));
    }
    if (!lane){ r0[w] = mnx; r1[w] = mny; r2[w] = mxx; r3[w] = mxy; }
    __syncthreads();
    if (w == 0){
        mnx = (lane < 8) ? r0[lane] : 1e30f;
        mny = (lane < 8) ? r1[lane] : 1e30f;
        mxx = (lane < 8) ? r2[lane] : -1e30f;
        mxy = (lane < 8) ? r3[lane] : -1e30f;
        #pragma unroll
        for (int o = 4; o; o >>= 1){
            mnx = fminf(mnx, __shfl_xor_sync(0xffffffffu, mnx, o));
            mny = fminf(mny, __shfl_xor_sync(0xffffffffu, mny, o));
            mxx = fmaxf(mxx, __shfl_xor_sync(0xffffffffu, mxx, o));
            mxy = fmaxf(mxy, __shfl_xor_sync(0xffffffffu, mxy, o));
        }
        if (!lane){
            atomicMin(&g_pminE[tensor][b][0], fenc(mnx));
            atomicMin(&g_pminE[tensor][b][1], fenc(mny));
            atomicMax(&g_pmaxE[tensor][b][0], fenc(mxx));
            atomicMax(&g_pmaxE[tensor][b][1], fenc(mxy));
        }
    }
}

// ---------------- K7: per-batch int min/max of grid indices ----------------
__global__ void __launch_bounds__(256) k7_idxminmax(const float* __restrict__ verts2){
    __shared__ int r0[8], r1[8], r2[8], r3[8];
    int tb = blockIdx.y;
    int tensor = tb >> 2, b = tb & 3;
    const float* p = tensor ? (verts2 + (size_t)b*NPTS*3) : (g_verts12 + (size_t)b*NPTS*3);
    float minx = fdec(g_pminE[tensor][b][0]);
    float miny = fdec(g_pminE[tensor][b][1]);
    float maxx = fdec(g_pmaxE[tensor][b][0]);
    float maxy = fdec(g_pmaxE[tensor][b][1]);
    float gs = __fdiv_rn(fmaxf(maxx - minx, maxy - miny), 221.0f);
    int i = blockIdx.x*256 + threadIdx.x;
    int mnx = 0x7FFFFFFF, mny = 0x7FFFFFFF;
    int mxx = (int)0x80000000, mxy = (int)0x80000000;
    if (i < NPTS){
        int ix = (int)floorf(__fdiv_rn(p[3*i]   - minx, gs));
        int iy = (int)floorf(__fdiv_rn(p[3*i+1] - miny, gs));
        mnx = mxx = ix; mny = mxy = iy;
    }
    int lane = threadIdx.x & 31, w = threadIdx.x >> 5;
    #pragma unroll
    for (int o = 16; o; o >>= 1){
        mnx = min(mnx, __shfl_xor_sync(0xffffffffu, mnx, o));
        mny = min(mny, __shfl_xor_sync(0xffffffffu, mny, o));
        mxx = max(mxx, __shfl_xor_sync(0xffffffffu, mxx, o));
        mxy = max(mxy, __shfl_xor_sync(0xffffffffu, mxy, o));
    }
    if (!lane){ r0[w] = mnx; r1[w] = mny; r2[w] = mxx; r3[w] = mxy; }
    __syncthreads();
    if (w == 0){
        mnx = (lane < 8) ? r0[lane] : 0x7FFFFFFF;
        mny = (lane < 8) ? r1[lane] : 0x7FFFFFFF;
        mxx = (lane < 8) ? r2[lane] : (int)0x80000000;
        mxy = (lane < 8) ? r3[lane] : (int)0x80000000;
        #pragma unroll
        for (int o = 4; o; o >>= 1){
            mnx = min(mnx, __shfl_xor_sync(0xffffffffu, mnx, o));
            mny = min(mny, __shfl_xor_sync(0xffffffffu, mny, o));
            mxx = max(mxx, __shfl_xor_sync(0xffffffffu, mxx, o));
            mxy = max(mxy, __shfl_xor_sync(0xffffffffu, mxy, o));
        }
        if (!lane){
            atomicMin(&g_iminI[tensor][b][0], mnx);
            atomicMin(&g_iminI[tensor][b][1], mny);
            atomicMax(&g_imaxI[tensor][b][0], mxx);
            atomicMax(&g_imaxI[tensor][b][1], mxy);
        }
    }
}

// ---------------- K8: scatter z into images ----------------
__global__ void __launch_bounds__(256) k8_scatter(const float* __restrict__ verts2){
    int tb = blockIdx.y;
    int tensor = tb >> 2, b = tb & 3;
    const float* p = tensor ? (verts2 + (size_t)b*NPTS*3) : (g_verts12 + (size_t)b*NPTS*3);
    int i = blockIdx.x*256 + threadIdx.x;
    if (i >= NPTS) return;
    float minx = fdec(g_pminE[tensor][b][0]);
    float miny = fdec(g_pminE[tensor][b][1]);
    float maxx = fdec(g_pmaxE[tensor][b][0]);
    float maxy = fdec(g_pmaxE[tensor][b][1]);
    float gs = __fdiv_rn(fmaxf(maxx - minx, maxy - miny), 221.0f);
    int ix = (int)floorf(__fdiv_rn(p[3*i]   - minx, gs));
    int iy = (int)floorf(__fdiv_rn(p[3*i+1] - miny, gs));
    float z = p[3*i+2];
    int cx = (g_imaxI[tensor][b][0] + g_iminI[tensor][b][0] + 2) >> 1;
    int cy = (g_imaxI[tensor][b][1] + g_iminI[tensor][b][1] + 2) >> 1;
    int ox = 111 - cx, oy = 111 - cy;
    float* img = g_img[tensor] + b*IMGSZ;
    #pragma unroll
    for (int t2 = 0; t2 < 25; t2++){
        int du = t2 / 5;
        int dv = t2 - du*5;
        int uu = ix + du - 1 + ox;
        int vv = iy + dv - 1 + oy;
        uu += (uu < 0) - (uu > IMG-1);
        vv += (vv < 0) - (vv > IMG-1);
        uu = max(0, min(IMG-1, uu));
        vv = max(0, min(IMG-1, vv));
        atomicAdd(&img[uu*IMG + vv], z);
    }
}

// ---------------- K9: image MSE ----------------
__global__ void __launch_bounds__(256) k9_imgloss(){
    int i = blockIdx.x*256 + threadIdx.x;
    float d = 0.f;
    if (i < BATCH*IMGSZ){
        float a = g_img[0][i], b2 = g_img[1][i];
        float s1 = 1.f/(1.f + __expf(-a));
        float s2 = 1.f/(1.f + __expf(-b2));
        float df = s1 - s2;
        d = df*df;
    }
    block_sum_atomic(d, &g_img_sum);
}

// ---------------- K10: finalize ----------------
__global__ void k10_final(float* out){
    if (threadIdx.x == 0 && blockIdx.x == 0){
        double self_l = g_self_sum / (double)(BATCH*NPTS);
        double def_l  = g_deform_sum / ((double)BATCH*NPTS*KNN*CDIM);
        double img_l  = g_img_sum / ((double)BATCH*IMGSZ);
        out[0] = (float)(self_l + img_l + def_l);
    }
}

// ---------------- launch ----------------
extern "C" void kernel_launch(void* const* d_in, const int* in_sizes, int n_in,
                              void* d_out, int out_size){
    const float* verts1 = (const float*)d_in[0];
    const float* verts2 = (const float*)d_in[1];
    const float* feat1  = (const float*)d_in[2];
    const float* feat2  = (const float*)d_in[3];
    float* out = (float*)d_out;

    cudaFuncSetAttribute(k2_softmax_mma, cudaFuncAttributeMaxDynamicSharedMemorySize, K2SMEM);

    k_init<<<1568, 256>>>();
    kprep<<<4995, 256>>>(feat1, feat2);
    k1_norms<<<4995, 256>>>(feat1, feat2);
    k2_softmax_mma<<<dim3(MTILES, NSPLIT, BATCH), K2_THREADS, K2SMEM>>>(verts2);
    k2b_merge<<<(BATCH*NPTS + 255)/256, 256>>>();
    k3_selfrec<<<dim3((NPTS+63)/64, BATCH), 256>>>(verts2);
    k4_topk<<<dim3((NPTS+63)/64, BATCH, 2), 256>>>(verts1);
    k4b_merge<<<(BATCH*NPTS + 255)/256, 256>>>();
    k5_deform<<<(BATCH*NPTS + 63)/64, 256>>>(feat1);
    k6_ptminmax<<<dim3((NPTS+255)/256, 2*BATCH), 256>>>(verts2);
    k7_idxminmax<<<dim3((NPTS+255)/256, 2*BATCH), 256>>>(verts2);
    k8_scatter<<<dim3((NPTS+255)/256, 2*BATCH), 256>>>(verts2);
    k9_imgloss<<<(BATCH*IMGSZ+255)/256, 256>>>();
    k10_final<<<1, 32>>>(out);
}

// round 11
// speedup vs baseline: 1.0608x; 1.0608x over previous
#include <cuda_runtime.h>
#include <cuda_bf16.h>
#include <cstdint>
#include <math.h>

typedef unsigned int u32;
typedef unsigned long long u64;

#define BATCH 4
#define NPTS 4995
#define CDIM 128
#define KNN 10
#define IMG 224
#define IMGSZ (IMG*IMG)

#define MT 128
#define MTILES 40
#define NSPLIT 4
#define CHUNK 1280
#define K2_THREADS 512

// K2 smem layout (bytes)
#define BBUF 34816          // one 64-row B buffer: hi 17408 + lo 17408
#define BLO 17408
#define AH_SM 0
#define AL_SM 34816
#define BB_SM 69632         // 4 buffers x 34816 = 139264
#define CI_SM 208896        // 4 x 1024
#define MG_SM 212992        // 128 x 5 floats
#define K2SMEM 215552

#define K3CH 2048

// ---------------- scratch ----------------
__device__ unsigned short g_f1hi[BATCH*NPTS*CDIM];
__device__ unsigned short g_f1lo[BATCH*NPTS*CDIM];
__device__ unsigned short g_f2hi[BATCH*NPTS*CDIM];
__device__ unsigned short g_f2lo[BATCH*NPTS*CDIM];
__device__ float g_nf1[BATCH*NPTS];
__device__ float g_nf2[BATCH*NPTS];
__device__ float g_pm[BATCH*NPTS*NSPLIT];
__device__ float g_ps[BATCH*NPTS*NSPLIT];
__device__ float g_px[BATCH*NPTS*NSPLIT];
__device__ float g_py[BATCH*NPTS*NSPLIT];
__device__ float g_pz[BATCH*NPTS*NSPLIT];
__device__ float g_verts12[BATCH*NPTS*3];
__device__ int   g_idx11[BATCH*NPTS*KNN];
__device__ float g_img[2][BATCH*IMGSZ];
__device__ unsigned g_pminE[2][BATCH][2];
__device__ unsigned g_pmaxE[2][BATCH][2];
__device__ int g_iminI[2][BATCH][2];
__device__ int g_imaxI[2][BATCH][2];
__device__ double g_self_sum;
__device__ double g_deform_sum;
__device__ double g_img_sum;

// ---------------- generic helpers ----------------
__device__ __forceinline__ unsigned fenc(float f){
    unsigned uu = __float_as_uint(f);
    return (uu & 0x80000000u) ? ~uu : (uu | 0x80000000u);
}
__device__ __forceinline__ float fdec(unsigned uu){
    return __uint_as_float((uu & 0x80000000u) ? (uu ^ 0x80000000u) : ~uu);
}
__device__ __forceinline__ float sqrt_approx(float x){
    float y; asm("sqrt.approx.f32 %0, %1;" : "=f"(y) : "f"(x)); return y;
}
__device__ __forceinline__ void block_sum_atomic(float v, double* target){
    __shared__ float red[32];
    int lane = threadIdx.x & 31, w = threadIdx.x >> 5;
    #pragma unroll
    for (int o = 16; o; o >>= 1) v += __shfl_xor_sync(0xffffffffu, v, o);
    if (!lane) red[w] = v;
    __syncthreads();
    if (w == 0){
        int nw = (blockDim.x + 31) >> 5;
        float s = (lane < nw) ? red[lane] : 0.f;
        #pragma unroll
        for (int o = 16; o; o >>= 1) s += __shfl_xor_sync(0xffffffffu, s, o);
        if (!lane) atomicAdd(target, (double)s);
    }
}
__device__ __forceinline__ u32 smem_u32(const void* p){
    u32 a;
    asm("{ .reg .u64 t; cvta.to.shared.u64 t, %1; cvt.u32.u64 %0, t; }" : "=r"(a) : "l"(p));
    return a;
}
__device__ __forceinline__ void bar_named(int id){
    asm volatile("bar.sync %0, 256;" :: "r"(id) : "memory");
}

// ---------------- mma.sync / ldmatrix wrappers ----------------
__device__ __forceinline__ void ldsm_x4(u32* r, u32 addr){
    asm volatile("ldmatrix.sync.aligned.m8n8.x4.shared.b16 {%0,%1,%2,%3}, [%4];"
        : "=r"(r[0]), "=r"(r[1]), "=r"(r[2]), "=r"(r[3]) : "r"(addr));
}
__device__ __forceinline__ void mma_bf16(float* d, const u32* a, u32 b0, u32 b1){
    asm volatile(
        "mma.sync.aligned.m16n8k16.row.col.f32.bf16.bf16.f32 "
        "{%0,%1,%2,%3}, {%4,%5,%6,%7}, {%8,%9}, {%0,%1,%2,%3};"
        : "+f"(d[0]), "+f"(d[1]), "+f"(d[2]), "+f"(d[3])
        : "r"(a[0]), "r"(a[1]), "r"(a[2]), "r"(a[3]), "r"(b0), "r"(b1));
}

// ---------------- K0: init ----------------
__global__ void k_init(){
    int i = blockIdx.x*blockDim.x + threadIdx.x;
    if (i < 2*BATCH*IMGSZ) ((float*)g_img)[i] = 0.0f;
    if (i == 0){ g_self_sum = 0.0; g_deform_sum = 0.0; g_img_sum = 0.0; }
    if (i < 16){
        ((unsigned*)g_pminE)[i] = 0xFFFFFFFFu;
        ((unsigned*)g_pmaxE)[i] = 0u;
        ((int*)g_iminI)[i] = 0x7FFFFFFF;
        ((int*)g_imaxI)[i] = (int)0x80000000;
    }
}

// ---------------- Kprep: double-bf16 split ----------------
__global__ void __launch_bounds__(256) kprep(const float* __restrict__ f1,
                                             const float* __restrict__ f2){
    const int half = BATCH*NPTS*CDIM/4;
    int i = blockIdx.x*256 + threadIdx.x;
    if (i >= 2*half) return;
    bool second = i >= half;
    int j = second ? i - half : i;
    float4 v = ((const float4*)(second ? f2 : f1))[j];
    unsigned short* hi = second ? g_f2hi : g_f1hi;
    unsigned short* lo = second ? g_f2lo : g_f1lo;
    float vv[4]; vv[0]=v.x; vv[1]=v.y; vv[2]=v.z; vv[3]=v.w;
    unsigned short hu[4], lu[4];
    #pragma unroll
    for (int c = 0; c < 4; c++){
        __nv_bfloat16 h = __float2bfloat16_rn(vv[c]);
        float r = vv[c] - __bfloat162float(h);
        __nv_bfloat16 l = __float2bfloat16_rn(r);
        hu[c] = __bfloat16_as_ushort(h);
        lu[c] = __bfloat16_as_ushort(l);
    }
    ((uint2*)hi)[j] = make_uint2((u32)hu[0] | ((u32)hu[1] << 16),
                                 (u32)hu[2] | ((u32)hu[3] << 16));
    ((uint2*)lo)[j] = make_uint2((u32)lu[0] | ((u32)lu[1] << 16),
                                 (u32)lu[2] | ((u32)lu[3] << 16));
}

// ---------------- K1: feature row norms ----------------
__global__ void __launch_bounds__(256) k1_norms(const float* __restrict__ f1,
                                                const float* __restrict__ f2){
    int gw = (blockIdx.x*blockDim.x + threadIdx.x) >> 5;
    int lane = threadIdx.x & 31;
    if (gw >= 2*BATCH*NPTS) return;
    const float* src; float* dst; int row;
    if (gw < BATCH*NPTS){ src = f1; dst = g_nf1; row = gw; }
    else { src = f2; dst = g_nf2; row = gw - BATCH*NPTS; }
    float4 v = *(const float4*)(src + (size_t)row*CDIM + lane*4);
    float s = v.x*v.x + v.y*v.y + v.z*v.z + v.w*v.w;
    #pragma unroll
    for (int o = 16; o; o >>= 1) s += __shfl_xor_sync(0xffffffffu, s, o);
    if (!lane) dst[row] = s;
}

// ---------------- K2: HMMA fused softmax, two warp-groups pipelined ----------------
__global__ void __launch_bounds__(K2_THREADS)
k2_softmax_mma(const float* __restrict__ verts2){
    extern __shared__ char smem[];
    const int tid = threadIdx.x;
    const int wid = tid >> 5, lane = tid & 31;
    const int grp = wid >> 3;         // 0 or 1
    const int gwid = wid & 7;         // warp within group: 16-row slice
    const int gtid = tid & 255;       // thread within group
    const int b = blockIdx.z, split = blockIdx.y, mt = blockIdx.x;
    const int n0 = mt * MT;
    const int cs = split * CHUNK;
    const int ce = min(cs + CHUNK, NPTS);
    const int T = (ce - cs + 63) >> 6;      // 64-wide tiles
    const int H = (T + 1) >> 1;
    const int tbase = grp ? H : 0;
    const int myT = grp ? (T - H) : H;
    const size_t bofs = (size_t)b * NPTS;
    const float* v2 = verts2 + bofs * 3;
    u32 sb = smem_u32(smem);

    // stage A tile (hi & lo), all 512 threads
    for (int i = tid; i < 2048; i += K2_THREADS){
        int row = i >> 4, c8 = i & 15;
        int n = n0 + row;
        uint4 vh = make_uint4(0u,0u,0u,0u);
        uint4 vl = make_uint4(0u,0u,0u,0u);
        if (n < NPTS){
            vh = *(const uint4*)(g_f1hi + ((bofs + n) << 7) + (c8 << 3));
            vl = *(const uint4*)(g_f1lo + ((bofs + n) << 7) + (c8 << 3));
        }
        *(uint4*)(smem + AH_SM + row*272 + c8*16) = vh;
        *(uint4*)(smem + AL_SM + row*272 + c8*16) = vl;
    }
    // each group stages its first B tile (64 rows) + colinfo
    if (myT > 0){
        int m0 = cs + tbase*64;
        char* bufb = smem + BB_SM + (grp*2 + 0)*BBUF;
        for (int i = gtid; i < 2048; i += 256){
            int row = i >> 5, c8 = i & 31;
            int m = m0 + row;
            uint4 v = make_uint4(0u,0u,0u,0u);
            const unsigned short* src = (c8 < 16) ? g_f2hi : g_f2lo;
            int cc8 = c8 & 15;
            if (m < ce) v = *(const uint4*)(src + ((bofs + m) << 7) + (cc8 << 3));
            *(uint4*)(bufb + ((c8 < 16) ? 0 : BLO) + row*272 + cc8*16) = v;
        }
        if (gtid < 64){
            int m = m0 + gtid;
            float4 ci;
            if (m < ce){ ci.x = g_nf2[bofs+m]; ci.y = v2[m*3]; ci.z = v2[m*3+1]; ci.w = v2[m*3+2]; }
            else { ci.x = 1e30f; ci.y = 0.f; ci.z = 0.f; ci.w = 0.f; }
            *(float4*)(smem + CI_SM + (grp*2 + 0)*1024 + gtid*16) = ci;
        }
    }
    __syncthreads();

    const u32 aRowOff = (u32)((gwid*16 + (lane & 15)) * 272 + (lane >> 4) * 16);
    const u32 aHa = sb + AH_SM + aRowOff;
    const u32 aLa = sb + AL_SM + aRowOff;
    const u32 bOff4 = (u32)(((lane & 7) + ((lane >> 4) << 3)) * 272 + (((lane >> 3) & 1) << 4));

    float nf10 = 0.f, nf11 = 0.f;
    const int r0g = n0 + gwid*16 + (lane >> 2);
    if (r0g < NPTS) nf10 = g_nf1[bofs + r0g];
    if (r0g + 8 < NPTS) nf11 = g_nf1[bofs + r0g + 8];

    float rm0=-1e30f, rs0=0.f, rx0=0.f, ry0=0.f, rz0=0.f;
    float rm1=-1e30f, rs1=0.f, rx1=0.f, ry1=0.f, rz1=0.f;

    for (int j = 0; j < myT; j++){
        // prefetch next tile of this group
        if (j + 1 < myT){
            int m0 = cs + (tbase + j + 1)*64;
            int nb = (j + 1) & 1;
            char* bufb = smem + BB_SM + (grp*2 + nb)*BBUF;
            for (int i = gtid; i < 2048; i += 256){
                int row = i >> 5, c8 = i & 31;
                int m = m0 + row;
                uint4 v = make_uint4(0u,0u,0u,0u);
                const unsigned short* src = (c8 < 16) ? g_f2hi : g_f2lo;
                int cc8 = c8 & 15;
                if (m < ce) v = *(const uint4*)(src + ((bofs + m) << 7) + (cc8 << 3));
                *(uint4*)(bufb + ((c8 < 16) ? 0 : BLO) + row*272 + cc8*16) = v;
            }
            if (gtid < 64){
                int m = m0 + gtid;
                float4 ci;
                if (m < ce){ ci.x = g_nf2[bofs+m]; ci.y = v2[m*3]; ci.z = v2[m*3+1]; ci.w = v2[m*3+2]; }
                else { ci.x = 1e30f; ci.y = 0.f; ci.z = 0.f; ci.w = 0.f; }
                *(float4*)(smem + CI_SM + (grp*2 + nb)*1024 + gtid*16) = ci;
            }
        }

        // MMA on current buffer
        float acc[32];
        #pragma unroll
        for (int i = 0; i < 32; i++) acc[i] = 0.f;
        const u32 bBase = sb + BB_SM + (u32)((grp*2 + (j & 1))*BBUF) + bOff4;
        #pragma unroll
        for (int ks = 0; ks < 8; ks++){
            u32 ah[4], al[4];
            ldsm_x4(ah, aHa + ks*32);
            ldsm_x4(al, aLa + ks*32);
            #pragma unroll
            for (int fp = 0; fp < 4; fp++){
                u32 bh[4], bl[4];
                u32 baddr = bBase + (u32)(fp*4352 + ks*32);
                ldsm_x4(bh, baddr);
                ldsm_x4(bl, baddr + BLO);
                mma_bf16(acc + fp*8,     ah, bh[0], bh[1]);
                mma_bf16(acc + fp*8,     ah, bl[0], bl[1]);
                mma_bf16(acc + fp*8,     al, bh[0], bh[1]);
                mma_bf16(acc + fp*8 + 4, ah, bh[2], bh[3]);
                mma_bf16(acc + fp*8 + 4, ah, bl[2], bl[3]);
                mma_bf16(acc + fp*8 + 4, al, bh[2], bh[3]);
            }
        }

        // online softmax epilogue
        const char* cib = smem + CI_SM + (grp*2 + (j & 1))*1024;
        float tm0 = -1e30f, tm1 = -1e30f;
        #pragma unroll
        for (int f = 0; f < 8; f++){
            int n = f*8 + (lane & 3)*2;
            float c0x = *(const float*)(cib + n*16);
            float c1x = *(const float*)(cib + n*16 + 16);
            float s0 = fmaxf(fmaf(-2.f, acc[f*4+0], nf10 + c0x), 1e-12f);
            float s1 = fmaxf(fmaf(-2.f, acc[f*4+1], nf10 + c1x), 1e-12f);
            float s2 = fmaxf(fmaf(-2.f, acc[f*4+2], nf11 + c0x), 1e-12f);
            float s3 = fmaxf(fmaf(-2.f, acc[f*4+3], nf11 + c1x), 1e-12f);
            acc[f*4+0] = -100.f*sqrt_approx(s0);
            acc[f*4+1] = -100.f*sqrt_approx(s1);
            acc[f*4+2] = -100.f*sqrt_approx(s2);
            acc[f*4+3] = -100.f*sqrt_approx(s3);
            tm0 = fmaxf(tm0, fmaxf(acc[f*4+0], acc[f*4+1]));
            tm1 = fmaxf(tm1, fmaxf(acc[f*4+2], acc[f*4+3]));
        }
        float nm0 = fmaxf(rm0, tm0), nm1 = fmaxf(rm1, tm1);
        float sc0 = __expf(rm0 - nm0), sc1 = __expf(rm1 - nm1);
        rs0 *= sc0; rx0 *= sc0; ry0 *= sc0; rz0 *= sc0; rm0 = nm0;
        rs1 *= sc1; rx1 *= sc1; ry1 *= sc1; rz1 *= sc1; rm1 = nm1;
        #pragma unroll
        for (int f = 0; f < 8; f++){
            int n = f*8 + (lane & 3)*2;
            float4 c0 = *(const float4*)(cib + n*16);
            float4 c1 = *(const float4*)(cib + n*16 + 16);
            float w0 = __expf(acc[f*4+0] - nm0);
            float w1 = __expf(acc[f*4+1] - nm0);
            float w2 = __expf(acc[f*4+2] - nm1);
            float w3 = __expf(acc[f*4+3] - nm1);
            rs0 += w0 + w1; rs1 += w2 + w3;
            rx0 = fmaf(w0, c0.y, fmaf(w1, c1.y, rx0));
            ry0 = fmaf(w0, c0.z, fmaf(w1, c1.z, ry0));
            rz0 = fmaf(w0, c0.w, fmaf(w1, c1.w, rz0));
            rx1 = fmaf(w2, c0.y, fmaf(w3, c1.y, rx1));
            ry1 = fmaf(w2, c0.z, fmaf(w3, c1.z, ry1));
            rz1 = fmaf(w2, c0.w, fmaf(w3, c1.w, rz1));
        }
        bar_named(1 + grp);
    }

    // merge across the 4 lanes of each row quad
    #pragma unroll
    for (int o = 1; o <= 2; o <<= 1){
        float om = __shfl_xor_sync(0xffffffffu, rm0, o);
        float os = __shfl_xor_sync(0xffffffffu, rs0, o);
        float ox = __shfl_xor_sync(0xffffffffu, rx0, o);
        float oy = __shfl_xor_sync(0xffffffffu, ry0, o);
        float oz = __shfl_xor_sync(0xffffffffu, rz0, o);
        float nm = fmaxf(rm0, om);
        float e1 = __expf(rm0 - nm), e2 = __expf(om - nm);
        rs0 = rs0*e1 + os*e2; rx0 = rx0*e1 + ox*e2;
        ry0 = ry0*e1 + oy*e2; rz0 = rz0*e1 + oz*e2; rm0 = nm;
        om = __shfl_xor_sync(0xffffffffu, rm1, o);
        os = __shfl_xor_sync(0xffffffffu, rs1, o);
        ox = __shfl_xor_sync(0xffffffffu, rx1, o);
        oy = __shfl_xor_sync(0xffffffffu, ry1, o);
        oz = __shfl_xor_sync(0xffffffffu, rz1, o);
        nm = fmaxf(rm1, om);
        e1 = __expf(rm1 - nm); e2 = __expf(om - nm);
        rs1 = rs1*e1 + os*e2; rx1 = rx1*e1 + ox*e2;
        ry1 = ry1*e1 + oy*e2; rz1 = rz1*e1 + oz*e2; rm1 = nm;
    }

    // cross-group merge through smem
    __syncthreads();
    float* mg = (float*)(smem + MG_SM);
    int rl0 = gwid*16 + (lane >> 2);
    if (grp == 1 && (lane & 3) == 0){
        mg[rl0*5+0] = rm0; mg[rl0*5+1] = rs0; mg[rl0*5+2] = rx0; mg[rl0*5+3] = ry0; mg[rl0*5+4] = rz0;
        mg[(rl0+8)*5+0] = rm1; mg[(rl0+8)*5+1] = rs1; mg[(rl0+8)*5+2] = rx1; mg[(rl0+8)*5+3] = ry1; mg[(rl0+8)*5+4] = rz1;
    }
    __syncthreads();
    if (grp == 0 && (lane & 3) == 0){
        float m2 = mg[rl0*5+0], s2 = mg[rl0*5+1], x2 = mg[rl0*5+2], y2 = mg[rl0*5+3], z2 = mg[rl0*5+4];
        float nm = fmaxf(rm0, m2);
        float e1 = __expf(rm0 - nm), e2 = __expf(m2 - nm);
        float S = rs0*e1 + s2*e2, X = rx0*e1 + x2*e2, Y = ry0*e1 + y2*e2, Z = rz0*e1 + z2*e2;
        int n = n0 + rl0;
        if (n < NPTS){
            size_t pi = (bofs + n)*NSPLIT + split;
            g_pm[pi] = nm; g_ps[pi] = S; g_px[pi] = X; g_py[pi] = Y; g_pz[pi] = Z;
        }
        m2 = mg[(rl0+8)*5+0]; s2 = mg[(rl0+8)*5+1]; x2 = mg[(rl0+8)*5+2]; y2 = mg[(rl0+8)*5+3]; z2 = mg[(rl0+8)*5+4];
        nm = fmaxf(rm1, m2);
        e1 = __expf(rm1 - nm); e2 = __expf(m2 - nm);
        S = rs1*e1 + s2*e2; X = rx1*e1 + x2*e2; Y = ry1*e1 + y2*e2; Z = rz1*e1 + z2*e2;
        n = n0 + rl0 + 8;
        if (n < NPTS){
            size_t pi = (bofs + n)*NSPLIT + split;
            g_pm[pi] = nm; g_ps[pi] = S; g_px[pi] = X; g_py[pi] = Y; g_pz[pi] = Z;
        }
    }
}

// ---------------- K2b: merge splits -> verts12 ----------------
__global__ void __launch_bounds__(256) k2b_merge(){
    int i = blockIdx.x*256 + threadIdx.x;
    if (i >= BATCH*NPTS) return;
    float m = -1e30f, s = 0.f, x = 0.f, y = 0.f, z = 0.f;
    #pragma unroll
    for (int sp = 0; sp < NSPLIT; sp++){
        size_t pi = (size_t)i*NSPLIT + sp;
        float m2 = g_pm[pi], s2 = g_ps[pi], x2 = g_px[pi], y2 = g_py[pi], z2 = g_pz[pi];
        float nm = fmaxf(m, m2);
        float a1 = __expf(m - nm), a2 = __expf(m2 - nm);
        s = s*a1 + s2*a2; x = x*a1 + x2*a2; y = y*a1 + y2*a2; z = z*a1 + z2*a2;
        m = nm;
    }
    float inv = 1.f / s;
    g_verts12[(size_t)i*3 + 0] = x*inv;
    g_verts12[(size_t)i*3 + 1] = y*inv;
    g_verts12[(size_t)i*3 + 2] = z*inv;
}

// ---------------- K3: self_rec ----------------
__global__ void __launch_bounds__(256) k3_selfrec(const float* __restrict__ verts2){
    __shared__ __align__(16) float sx[K3CH+4];
    __shared__ __align__(16) float sy[K3CH+4];
    __shared__ __align__(16) float sz[K3CH+4];
    int b = blockIdx.y;
    int part = threadIdx.x & 3;
    int nl = threadIdx.x >> 2;
    int n = blockIdx.x*64 + nl;
    bool valid = n < NPTS;
    float vx=0.f, vy=0.f, vz=0.f;
    if (valid){
        vx = g_verts12[((size_t)b*NPTS + n)*3 + 0];
        vy = g_verts12[((size_t)b*NPTS + n)*3 + 1];
        vz = g_verts12[((size_t)b*NPTS + n)*3 + 2];
    }
    const float* v2 = verts2 + (size_t)b*NPTS*3;
    float best = 3.4e38f;
    for (int m0 = 0; m0 < NPTS; m0 += K3CH){
        int cnt = min(K3CH, NPTS - m0);
        __syncthreads();
        for (int i = threadIdx.x; i < cnt; i += 256){
            sx[i] = v2[(m0+i)*3]; sy[i] = v2[(m0+i)*3+1]; sz[i] = v2[(m0+i)*3+2];
        }
        if (threadIdx.x < 4){
            sx[cnt+threadIdx.x] = 1e30f; sy[cnt+threadIdx.x] = 1e30f; sz[cnt+threadIdx.x] = 1e30f;
        }
        __syncthreads();
        int ng = (cnt + 3) >> 2;
        for (int g = part; g < ng; g += 4){
            float4 X = *(const float4*)(sx + 4*g);
            float4 Y = *(const float4*)(sy + 4*g);
            float4 Z = *(const float4*)(sz + 4*g);
            float dx0 = vx-X.x, dy0 = vy-Y.x, dz0 = vz-Z.x;
            float dx1 = vx-X.y, dy1 = vy-Y.y, dz1 = vz-Z.y;
            float dx2 = vx-X.z, dy2 = vy-Y.z, dz2 = vz-Z.z;
            float dx3 = vx-X.w, dy3 = vy-Y.w, dz3 = vz-Z.w;
            float d0 = fmaf(dx0,dx0, fmaf(dy0,dy0, dz0*dz0));
            float d1 = fmaf(dx1,dx1, fmaf(dy1,dy1, dz1*dz1));
            float d2 = fmaf(dx2,dx2, fmaf(dy2,dy2, dz2*dz2));
            float d3 = fmaf(dx3,dx3, fmaf(dy3,dy3, dz3*dz3));
            best = fminf(best, fminf(fminf(d0,d1), fminf(d2,d3)));
        }
    }
    best = fminf(best, __shfl_xor_sync(0xffffffffu, best, 1));
    best = fminf(best, __shfl_xor_sync(0xffffffffu, best, 2));
    float contrib = (part == 0 && valid) ? best : 0.f;
    __syncthreads();
    block_sum_atomic(contrib, &g_self_sum);
}

// ---------------- K4: top-10 nearest neighbors (SoA + group prefilter) ----------------
__global__ void __launch_bounds__(256) k4_topk(const float* __restrict__ verts1){
    __shared__ __align__(16) float sx[K3CH+4];
    __shared__ __align__(16) float sy[K3CH+4];
    __shared__ __align__(16) float sz[K3CH+4];
    __shared__ float smval[256][10];
    __shared__ int   smidx[256][10];
    int b = blockIdx.y;
    int part = threadIdx.x & 3;
    int nl = threadIdx.x >> 2;
    int n = blockIdx.x*64 + nl;
    const float* v1 = verts1 + (size_t)b*NPTS*3;
    float vx=0.f, vy=0.f, vz=0.f;
    if (n < NPTS){ vx = v1[3*n]; vy = v1[3*n+1]; vz = v1[3*n+2]; }
    float val[10]; int idx[10];
    #pragma unroll
    for (int q = 0; q < 10; q++){ val[q] = 3.4e38f; idx[q] = 0; }
    for (int m0 = 0; m0 < NPTS; m0 += K3CH){
        int cnt = min(K3CH, NPTS - m0);
        __syncthreads();
        for (int i = threadIdx.x; i < cnt; i += 256){
            sx[i] = v1[(m0+i)*3]; sy[i] = v1[(m0+i)*3+1]; sz[i] = v1[(m0+i)*3+2];
        }
        if (threadIdx.x < 4){
            sx[cnt+threadIdx.x] = 1e30f; sy[cnt+threadIdx.x] = 1e30f; sz[cnt+threadIdx.x] = 1e30f;
        }
        __syncthreads();
        int ng = (cnt + 3) >> 2;
        for (int g = part; g < ng; g += 4){
            float4 X = *(const float4*)(sx + 4*g);
            float4 Y = *(const float4*)(sy + 4*g);
            float4 Z = *(const float4*)(sz + 4*g);
            float dx0 = vx-X.x, dy0 = vy-Y.x, dz0 = vz-Z.x;
            float dx1 = vx-X.y, dy1 = vy-Y.y, dz1 = vz-Z.y;
            float dx2 = vx-X.z, dy2 = vy-Y.z, dz2 = vz-Z.z;
            float dx3 = vx-X.w, dy3 = vy-Y.w, dz3 = vz-Z.w;
            float d0 = fmaf(dx0,dx0, fmaf(dy0,dy0, dz0*dz0));
            float d1 = fmaf(dx1,dx1, fmaf(dy1,dy1, dz1*dz1));
            float d2 = fmaf(dx2,dx2, fmaf(dy2,dy2, dz2*dz2));
            float d3 = fmaf(dx3,dx3, fmaf(dy3,dy3, dz3*dz3));
            float gm = fminf(fminf(d0,d1), fminf(d2,d3));
            if (gm < val[9]){
                float ds[4]; ds[0]=d0; ds[1]=d1; ds[2]=d2; ds[3]=d3;
                #pragma unroll
                for (int k = 0; k < 4; k++){
                    if (ds[k] < val[9]){
                        float cv = ds[k]; int ci = m0 + 4*g + k;
                        #pragma unroll
                        for (int q = 0; q < 10; q++){
                            if (cv < val[q]){
                                float tv = val[q]; int ti = idx[q];
                                val[q] = cv; idx[q] = ci; cv = tv; ci = ti;
                            }
                        }
                    }
                }
            }
        }
    }
    #pragma unroll
    for (int q = 0; q < 10; q++){ smval[threadIdx.x][q] = val[q]; smidx[threadIdx.x][q] = idx[q]; }
    __syncthreads();
    if (part == 0 && n < NPTS){
        int h0=0,h1=0,h2=0,h3=0;
        int base = threadIdx.x;
        int out = (b*NPTS + n)*KNN;
        #pragma unroll
        for (int q = 0; q < 10; q++){
            float b0 = smval[base][h0],   b1 = smval[base+1][h1];
            float b2 = smval[base+2][h2], b3 = smval[base+3][h3];
            float mm = fminf(fminf(b0,b1), fminf(b2,b3));
            int chosen;
            if (mm == b0){ chosen = smidx[base][h0];   h0++; }
            else if (mm == b1){ chosen = smidx[base+1][h1]; h1++; }
            else if (mm == b2){ chosen = smidx[base+2][h2]; h2++; }
            else { chosen = smidx[base+3][h3]; h3++; }
            g_idx11[out + q] = chosen;
        }
    }
}

// ---------------- K5: deform feature MSE (warp-per-point) ----------------
__global__ void __launch_bounds__(256) k5_deform(const float* __restrict__ feat1){
    int w = threadIdx.x >> 5, lane = threadIdx.x & 31;
    int base = blockIdx.x*64 + w*8;
    float acc = 0.f;
    #pragma unroll
    for (int p = 0; p < 8; p++){
        int bn = base + p;
        if (bn < BATCH*NPTS){
            int b = bn / NPTS, n = bn - b*NPTS;
            const float* f1 = feat1 + (size_t)b*NPTS*CDIM;
            float4 fc = *(const float4*)(f1 + (size_t)n*CDIM + lane*4);
            #pragma unroll
            for (int q = 0; q < KNN; q++){
                int m = g_idx11[bn*KNN + q];
                float4 fm = *(const float4*)(f1 + (size_t)m*CDIM + lane*4);
                float d0 = fm.x - fc.x, d1 = fm.y - fc.y;
                float d2 = fm.z - fc.z, d3 = fm.w - fc.w;
                acc = fmaf(d0,d0, acc); acc = fmaf(d1,d1, acc);
                acc = fmaf(d2,d2, acc); acc = fmaf(d3,d3, acc);
            }
        }
    }
    block_sum_atomic(acc, &g_deform_sum);
}

// ---------------- K6: per-batch xy min/max ----------------
__global__ void __launch_bounds__(256) k6_ptminmax(const float* __restrict__ verts2){
    __shared__ float r0[8], r1[8], r2[8], r3[8];
    int tb = blockIdx.y;
    int tensor = tb >> 2, b = tb & 3;
    const float* p = tensor ? (verts2 + (size_t)b*NPTS*3) : (g_verts12 + (size_t)b*NPTS*3);
    int i = blockIdx.x*256 + threadIdx.x;
    float mnx = 1e30f, mny = 1e30f, mxx = -1e30f, mxy = -1e30f;
    if (i < NPTS){ mnx = mxx = p[3*i]; mny = mxy = p[3*i+1]; }
    int lane = threadIdx.x & 31, w = threadIdx.x >> 5;
    #pragma unroll
    for (int o = 16; o; o >>= 1){
        mnx = fminf(mnx, __shfl_xor_sync(0xffffffffu, mnx, o));
        mny = fminf(mny, __shfl_xor_sync(0xffffffffu, mny, o));
        mxx = fmaxf(mxx, __shfl_xor_sync(0xffffffffu, mxx, o));
        mxy = fmaxf(mxy, __shfl_xor_sync(0xffffffffu, mxy, o));
    }
    if (!lane){ r0[w] = mnx; r1[w] = mny; r2[w] = mxx; r3[w] = mxy; }
    __syncthreads();
    if (w == 0){
        mnx = (lane < 8) ? r0[lane] : 1e30f;
        mny = (lane < 8) ? r1[lane] : 1e30f;
        mxx = (lane < 8) ? r2[lane] : -1e30f;
        mxy = (lane < 8) ? r3[lane] : -1e30f;
        #pragma unroll
        for (int o = 4; o; o >>= 1){
            mnx = fminf(mnx, __shfl_xor_sync(0xffffffffu, mnx, o));
            mny = fminf(mny, __shfl_xor_sync(0xffffffffu, mny, o));
            mxx = fmaxf(mxx, __shfl_xor_sync(0xffffffffu, mxx, o));
            mxy = fmaxf(mxy, __shfl_xor_sync(0xffffffffu, mxy, o));
        }
        if (!lane){
            atomicMin(&g_pminE[tensor][b][0], fenc(mnx));
            atomicMin(&g_pminE[tensor][b][1], fenc(mny));
            atomicMax(&g_pmaxE[tensor][b][0], fenc(mxx));
            atomicMax(&g_pmaxE[tensor][b][1], fenc(mxy));
        }
    }
}

// ---------------- K7: per-batch int min/max of grid indices ----------------
__global__ void __launch_bounds__(256) k7_idxminmax(const float* __restrict__ verts2){
    __shared__ int r0[8], r1[8], r2[8], r3[8];
    int tb = blockIdx.y;
    int tensor = tb >> 2, b = tb & 3;
    const float* p = tensor ? (verts2 + (size_t)b*NPTS*3) : (g_verts12 + (size_t)b*NPTS*3);
    float minx = fdec(g_pminE[tensor][b][0]);
    float miny = fdec(g_pminE[tensor][b][1]);
    float maxx = fdec(g_pmaxE[tensor][b][0]);
    float maxy = fdec(g_pmaxE[tensor][b][1]);
    float gs = __fdiv_rn(fmaxf(maxx - minx, maxy - miny), 221.0f);
    int i = blockIdx.x*256 + threadIdx.x;
    int mnx = 0x7FFFFFFF, mny = 0x7FFFFFFF;
    int mxx = (int)0x80000000, mxy = (int)0x80000000;
    if (i < NPTS){
        int ix = (int)floorf(__fdiv_rn(p[3*i]   - minx, gs));
        int iy = (int)floorf(__fdiv_rn(p[3*i+1] - miny, gs));
        mnx = mxx = ix; mny = mxy = iy;
    }
    int lane = threadIdx.x & 31, w = threadIdx.x >> 5;
    #pragma unroll
    for (int o = 16; o; o >>= 1){
        mnx = min(mnx, __shfl_xor_sync(0xffffffffu, mnx, o));
        mny = min(mny, __shfl_xor_sync(0xffffffffu, mny, o));
        mxx = max(mxx, __shfl_xor_sync(0xffffffffu, mxx, o));
        mxy = max(mxy, __shfl_xor_sync(0xffffffffu, mxy, o));
    }
    if (!lane){ r0[w] = mnx; r1[w] = mny; r2[w] = mxx; r3[w] = mxy; }
    __syncthreads();
    if (w == 0){
        mnx = (lane < 8) ? r0[lane] : 0x7FFFFFFF;
        mny = (lane < 8) ? r1[lane] : 0x7FFFFFFF;
        mxx = (lane < 8) ? r2[lane] : (int)0x80000000;
        mxy = (lane < 8) ? r3[lane] : (int)0x80000000;
        #pragma unroll
        for (int o = 4; o; o >>= 1){
            mnx = min(mnx, __shfl_xor_sync(0xffffffffu, mnx, o));
            mny = min(mny, __shfl_xor_sync(0xffffffffu, mny, o));
            mxx = max(mxx, __shfl_xor_sync(0xffffffffu, mxx, o));
            mxy = max(mxy, __shfl_xor_sync(0xffffffffu, mxy, o));
        }
        if (!lane){
            atomicMin(&g_iminI[tensor][b][0], mnx);
            atomicMin(&g_iminI[tensor][b][1], mny);
            atomicMax(&g_imaxI[tensor][b][0], mxx);
            atomicMax(&g_imaxI[tensor][b][1], mxy);
        }
    }
}

// ---------------- K8: scatter z into images ----------------
__global__ void __launch_bounds__(256) k8_scatter(const float* __restrict__ verts2){
    int tb = blockIdx.y;
    int tensor = tb >> 2, b = tb & 3;
    const float* p = tensor ? (verts2 + (size_t)b*NPTS*3) : (g_verts12 + (size_t)b*NPTS*3);
    int i = blockIdx.x*256 + threadIdx.x;
    if (i >= NPTS) return;
    float minx = fdec(g_pminE[tensor][b][0]);
    float miny = fdec(g_pminE[tensor][b][1]);
    float maxx = fdec(g_pmaxE[tensor][b][0]);
    float maxy = fdec(g_pmaxE[tensor][b][1]);
    float gs = __fdiv_rn(fmaxf(maxx - minx, maxy - miny), 221.0f);
    int ix = (int)floorf(__fdiv_rn(p[3*i]   - minx, gs));
    int iy = (int)floorf(__fdiv_rn(p[3*i+1] - miny, gs));
    float z = p[3*i+2];
    int cx = (g_imaxI[tensor][b][0] + g_iminI[tensor][b][0] + 2) >> 1;
    int cy = (g_imaxI[tensor][b][1] + g_iminI[tensor][b][1] + 2) >> 1;
    int ox = 111 - cx, oy = 111 - cy;
    float* img = g_img[tensor] + b*IMGSZ;
    #pragma unroll
    for (int t2 = 0; t2 < 25; t2++){
        int du = t2 / 5;
        int dv = t2 - du*5;
        int uu = ix + du - 1 + ox;
        int vv = iy + dv - 1 + oy;
        uu += (uu < 0) - (uu > IMG-1);
        vv += (vv < 0) - (vv > IMG-1);
        uu = max(0, min(IMG-1, uu));
        vv = max(0, min(IMG-1, vv));
        atomicAdd(&img[uu*IMG + vv], z);
    }
}

// ---------------- K9: image MSE ----------------
__global__ void __launch_bounds__(256) k9_imgloss(){
    int i = blockIdx.x*256 + threadIdx.x;
    float d = 0.f;
    if (i < BATCH*IMGSZ){
        float a = g_img[0][i], b2 = g_img[1][i];
        float s1 = 1.f/(1.f + __expf(-a));
        float s2 = 1.f/(1.f + __expf(-b2));
        float df = s1 - s2;
        d = df*df;
    }
    block_sum_atomic(d, &g_img_sum);
}

// ---------------- K10: finalize ----------------
__global__ void k10_final(float* out){
    if (threadIdx.x == 0 && blockIdx.x == 0){
        double self_l = g_self_sum / (double)(BATCH*NPTS);
        double def_l  = g_deform_sum / ((double)BATCH*NPTS*KNN*CDIM);
        double img_l  = g_img_sum / ((double)BATCH*IMGSZ);
        out[0] = (float)(self_l + img_l + def_l);
    }
}

// ---------------- launch ----------------
extern "C" void kernel_launch(void* const* d_in, const int* in_sizes, int n_in,
                              void* d_out, int out_size){
    const float* verts1 = (const float*)d_in[0];
    const float* verts2 = (const float*)d_in[1];
    const float* feat1  = (const float*)d_in[2];
    const float* feat2  = (const float*)d_in[3];
    float* out = (float*)d_out;

    cudaFuncSetAttribute(k2_softmax_mma, cudaFuncAttributeMaxDynamicSharedMemorySize, K2SMEM);

    k_init<<<1568, 256>>>();
    kprep<<<4995, 256>>>(feat1, feat2);
    k1_norms<<<4995, 256>>>(feat1, feat2);
    k2_softmax_mma<<<dim3(MTILES, NSPLIT, BATCH), K2_THREADS, K2SMEM>>>(verts2);
    k2b_merge<<<(BATCH*NPTS + 255)/256, 256>>>();
    k3_selfrec<<<dim3((NPTS+63)/64, BATCH), 256>>>(verts2);
    k4_topk<<<dim3((NPTS+63)/64, BATCH), 256>>>(verts1);
    k5_deform<<<(BATCH*NPTS + 63)/64, 256>>>(feat1);
    k6_ptminmax<<<dim3((NPTS+255)/256, 2*BATCH), 256>>>(verts2);
    k7_idxminmax<<<dim3((NPTS+255)/256, 2*BATCH), 256>>>(verts2);
    k8_scatter<<<dim3((NPTS+255)/256, 2*BATCH), 256>>>(verts2);
    k9_imgloss<<<(BATCH*IMGSZ+255)/256, 256>>>();
    k10_final<<<1, 32>>>(out);
}

// round 12
// speedup vs baseline: 1.0872x; 1.0249x over previous
#include <cuda_runtime.h>
#include <cuda_bf16.h>
#include <cstdint>
#include <math.h>

typedef unsigned int u32;
typedef unsigned long long u64;

#define BATCH 4
#define NPTS 4995
#define CDIM 128
#define KNN 10
#define IMG 224
#define IMGSZ (IMG*IMG)

#define MT 128
#define MTILES 40
#define NSPLIT 8
#define CHUNK 640
#define K2_THREADS 512

// K2 smem layout (bytes)
#define BBUF 34816          // one 64-row B buffer: hi 17408 + lo 17408
#define BLO 17408
#define AH_SM 0
#define AL_SM 34816
#define BB_SM 69632         // 4 buffers x 34816 = 139264
#define CI_SM 208896        // 4 x 1024
#define MG_SM 212992        // 128 x 5 floats
#define K2SMEM 215552

#define K3CH 2048

// ---------------- scratch ----------------
__device__ unsigned short g_f1hi[BATCH*NPTS*CDIM];
__device__ unsigned short g_f1lo[BATCH*NPTS*CDIM];
__device__ unsigned short g_f2hi[BATCH*NPTS*CDIM];
__device__ unsigned short g_f2lo[BATCH*NPTS*CDIM];
__device__ float g_nf1[BATCH*NPTS];
__device__ float g_nf2[BATCH*NPTS];
__device__ float g_pm[BATCH*NPTS*NSPLIT];
__device__ float g_ps[BATCH*NPTS*NSPLIT];
__device__ float g_px[BATCH*NPTS*NSPLIT];
__device__ float g_py[BATCH*NPTS*NSPLIT];
__device__ float g_pz[BATCH*NPTS*NSPLIT];
__device__ float g_verts12[BATCH*NPTS*3];
__device__ int   g_idx11[BATCH*NPTS*KNN];
__device__ float g_img[2][BATCH*IMGSZ];
__device__ float g_mmf[2][BATCH][4];   // minx,miny,maxx,maxy
__device__ int   g_oxy[2][BATCH][2];   // ox, oy
__device__ double g_self_sum;
__device__ double g_deform_sum;
__device__ double g_img_sum;

// ---------------- generic helpers ----------------
__device__ __forceinline__ float sqrt_approx(float x){
    float y; asm("sqrt.approx.f32 %0, %1;" : "=f"(y) : "f"(x)); return y;
}
__device__ __forceinline__ void block_sum_atomic(float v, double* target){
    __shared__ float red[32];
    int lane = threadIdx.x & 31, w = threadIdx.x >> 5;
    #pragma unroll
    for (int o = 16; o; o >>= 1) v += __shfl_xor_sync(0xffffffffu, v, o);
    if (!lane) red[w] = v;
    __syncthreads();
    if (w == 0){
        int nw = (blockDim.x + 31) >> 5;
        float s = (lane < nw) ? red[lane] : 0.f;
        #pragma unroll
        for (int o = 16; o; o >>= 1) s += __shfl_xor_sync(0xffffffffu, s, o);
        if (!lane) atomicAdd(target, (double)s);
    }
}
__device__ __forceinline__ u32 smem_u32(const void* p){
    u32 a;
    asm("{ .reg .u64 t; cvta.to.shared.u64 t, %1; cvt.u32.u64 %0, t; }" : "=r"(a) : "l"(p));
    return a;
}
__device__ __forceinline__ void bar_named(int id){
    asm volatile("bar.sync %0, 256;" :: "r"(id) : "memory");
}

// ---------------- mma.sync / ldmatrix wrappers ----------------
__device__ __forceinline__ void ldsm_x4(u32* r, u32 addr){
    asm volatile("ldmatrix.sync.aligned.m8n8.x4.shared.b16 {%0,%1,%2,%3}, [%4];"
        : "=r"(r[0]), "=r"(r[1]), "=r"(r[2]), "=r"(r[3]) : "r"(addr));
}
__device__ __forceinline__ void mma_bf16(float* d, const u32* a, u32 b0, u32 b1){
    asm volatile(
        "mma.sync.aligned.m16n8k16.row.col.f32.bf16.bf16.f32 "
        "{%0,%1,%2,%3}, {%4,%5,%6,%7}, {%8,%9}, {%0,%1,%2,%3};"
        : "+f"(d[0]), "+f"(d[1]), "+f"(d[2]), "+f"(d[3])
        : "r"(a[0]), "r"(a[1]), "r"(a[2]), "r"(a[3]), "r"(b0), "r"(b1));
}

// ---------------- K_pre: init + double-bf16 split + row norms ----------------
__global__ void __launch_bounds__(256) k_pre(const float* __restrict__ f1,
                                             const float* __restrict__ f2){
    int tid = threadIdx.x;
    int i = blockIdx.x*256 + tid;

    // init images + sums
    if (i < 2*BATCH*IMGSZ) ((float*)g_img)[i] = 0.0f;
    if (i == 0){ g_self_sum = 0.0; g_deform_sum = 0.0; g_img_sum = 0.0; }

    // double-bf16 split
    const int half = BATCH*NPTS*CDIM/4;
    if (i < 2*half){
        bool second = i >= half;
        int j = second ? i - half : i;
        float4 v = ((const float4*)(second ? f2 : f1))[j];
        unsigned short* hi = second ? g_f2hi : g_f1hi;
        unsigned short* lo = second ? g_f2lo : g_f1lo;
        float vv[4]; vv[0]=v.x; vv[1]=v.y; vv[2]=v.z; vv[3]=v.w;
        unsigned short hu[4], lu[4];
        #pragma unroll
        for (int c = 0; c < 4; c++){
            __nv_bfloat16 h = __float2bfloat16_rn(vv[c]);
            float r = vv[c] - __bfloat162float(h);
            __nv_bfloat16 l = __float2bfloat16_rn(r);
            hu[c] = __bfloat16_as_ushort(h);
            lu[c] = __bfloat16_as_ushort(l);
        }
        ((uint2*)hi)[j] = make_uint2((u32)hu[0] | ((u32)hu[1] << 16),
                                     (u32)hu[2] | ((u32)hu[3] << 16));
        ((uint2*)lo)[j] = make_uint2((u32)lu[0] | ((u32)lu[1] << 16),
                                     (u32)lu[2] | ((u32)lu[3] << 16));
    }

    // row norms (warp per row)
    int gw = i >> 5;
    int lane = tid & 31;
    if (gw < 2*BATCH*NPTS){
        const float* src; float* dst; int row;
        if (gw < BATCH*NPTS){ src = f1; dst = g_nf1; row = gw; }
        else { src = f2; dst = g_nf2; row = gw - BATCH*NPTS; }
        float4 v = *(const float4*)(src + (size_t)row*CDIM + lane*4);
        float s = v.x*v.x + v.y*v.y + v.z*v.z + v.w*v.w;
        #pragma unroll
        for (int o = 16; o; o >>= 1) s += __shfl_xor_sync(0xffffffffu, s, o);
        if (!lane) dst[row] = s;
    }
}

// ---------------- K2: HMMA fused softmax, two warp-groups pipelined ----------------
__global__ void __launch_bounds__(K2_THREADS)
k2_softmax_mma(const float* __restrict__ verts2){
    extern __shared__ char smem[];
    const int tid = threadIdx.x;
    const int wid = tid >> 5, lane = tid & 31;
    const int grp = wid >> 3;
    const int gwid = wid & 7;
    const int gtid = tid & 255;
    const int b = blockIdx.z, split = blockIdx.y, mt = blockIdx.x;
    const int n0 = mt * MT;
    const int cs = split * CHUNK;
    const int ce = min(cs + CHUNK, NPTS);
    const int T = (ce - cs + 63) >> 6;
    const int H = (T + 1) >> 1;
    const int tbase = grp ? H : 0;
    const int myT = grp ? (T - H) : H;
    const size_t bofs = (size_t)b * NPTS;
    const float* v2 = verts2 + bofs * 3;
    u32 sb = smem_u32(smem);

    for (int i = tid; i < 2048; i += K2_THREADS){
        int row = i >> 4, c8 = i & 15;
        int n = n0 + row;
        uint4 vh = make_uint4(0u,0u,0u,0u);
        uint4 vl = make_uint4(0u,0u,0u,0u);
        if (n < NPTS){
            vh = *(const uint4*)(g_f1hi + ((bofs + n) << 7) + (c8 << 3));
            vl = *(const uint4*)(g_f1lo + ((bofs + n) << 7) + (c8 << 3));
        }
        *(uint4*)(smem + AH_SM + row*272 + c8*16) = vh;
        *(uint4*)(smem + AL_SM + row*272 + c8*16) = vl;
    }
    if (myT > 0){
        int m0 = cs + tbase*64;
        char* bufb = smem + BB_SM + (grp*2 + 0)*BBUF;
        for (int i = gtid; i < 2048; i += 256){
            int row = i >> 5, c8 = i & 31;
            int m = m0 + row;
            uint4 v = make_uint4(0u,0u,0u,0u);
            const unsigned short* src = (c8 < 16) ? g_f2hi : g_f2lo;
            int cc8 = c8 & 15;
            if (m < ce) v = *(const uint4*)(src + ((bofs + m) << 7) + (cc8 << 3));
            *(uint4*)(bufb + ((c8 < 16) ? 0 : BLO) + row*272 + cc8*16) = v;
        }
        if (gtid < 64){
            int m = m0 + gtid;
            float4 ci;
            if (m < ce){ ci.x = g_nf2[bofs+m]; ci.y = v2[m*3]; ci.z = v2[m*3+1]; ci.w = v2[m*3+2]; }
            else { ci.x = 1e30f; ci.y = 0.f; ci.z = 0.f; ci.w = 0.f; }
            *(float4*)(smem + CI_SM + (grp*2 + 0)*1024 + gtid*16) = ci;
        }
    }
    __syncthreads();

    const u32 aRowOff = (u32)((gwid*16 + (lane & 15)) * 272 + (lane >> 4) * 16);
    const u32 aHa = sb + AH_SM + aRowOff;
    const u32 aLa = sb + AL_SM + aRowOff;
    const u32 bOff4 = (u32)(((lane & 7) + ((lane >> 4) << 3)) * 272 + (((lane >> 3) & 1) << 4));

    float nf10 = 0.f, nf11 = 0.f;
    const int r0g = n0 + gwid*16 + (lane >> 2);
    if (r0g < NPTS) nf10 = g_nf1[bofs + r0g];
    if (r0g + 8 < NPTS) nf11 = g_nf1[bofs + r0g + 8];

    float rm0=-1e30f, rs0=0.f, rx0=0.f, ry0=0.f, rz0=0.f;
    float rm1=-1e30f, rs1=0.f, rx1=0.f, ry1=0.f, rz1=0.f;

    for (int j = 0; j < myT; j++){
        if (j + 1 < myT){
            int m0 = cs + (tbase + j + 1)*64;
            int nb = (j + 1) & 1;
            char* bufb = smem + BB_SM + (grp*2 + nb)*BBUF;
            for (int i = gtid; i < 2048; i += 256){
                int row = i >> 5, c8 = i & 31;
                int m = m0 + row;
                uint4 v = make_uint4(0u,0u,0u,0u);
                const unsigned short* src = (c8 < 16) ? g_f2hi : g_f2lo;
                int cc8 = c8 & 15;
                if (m < ce) v = *(const uint4*)(src + ((bofs + m) << 7) + (cc8 << 3));
                *(uint4*)(bufb + ((c8 < 16) ? 0 : BLO) + row*272 + cc8*16) = v;
            }
            if (gtid < 64){
                int m = m0 + gtid;
                float4 ci;
                if (m < ce){ ci.x = g_nf2[bofs+m]; ci.y = v2[m*3]; ci.z = v2[m*3+1]; ci.w = v2[m*3+2]; }
                else { ci.x = 1e30f; ci.y = 0.f; ci.z = 0.f; ci.w = 0.f; }
                *(float4*)(smem + CI_SM + (grp*2 + nb)*1024 + gtid*16) = ci;
            }
        }

        float acc[32];
        #pragma unroll
        for (int i = 0; i < 32; i++) acc[i] = 0.f;
        const u32 bBase = sb + BB_SM + (u32)((grp*2 + (j & 1))*BBUF) + bOff4;
        #pragma unroll
        for (int ks = 0; ks < 8; ks++){
            u32 ah[4], al[4];
            ldsm_x4(ah, aHa + ks*32);
            ldsm_x4(al, aLa + ks*32);
            #pragma unroll
            for (int fp = 0; fp < 4; fp++){
                u32 bh[4], bl[4];
                u32 baddr = bBase + (u32)(fp*4352 + ks*32);
                ldsm_x4(bh, baddr);
                ldsm_x4(bl, baddr + BLO);
                mma_bf16(acc + fp*8,     ah, bh[0], bh[1]);
                mma_bf16(acc + fp*8,     ah, bl[0], bl[1]);
                mma_bf16(acc + fp*8,     al, bh[0], bh[1]);
                mma_bf16(acc + fp*8 + 4, ah, bh[2], bh[3]);
                mma_bf16(acc + fp*8 + 4, ah, bl[2], bl[3]);
                mma_bf16(acc + fp*8 + 4, al, bh[2], bh[3]);
            }
        }

        const char* cib = smem + CI_SM + (grp*2 + (j & 1))*1024;
        float tm0 = -1e30f, tm1 = -1e30f;
        #pragma unroll
        for (int f = 0; f < 8; f++){
            int n = f*8 + (lane & 3)*2;
            float c0x = *(const float*)(cib + n*16);
            float c1x = *(const float*)(cib + n*16 + 16);
            float s0 = fmaxf(fmaf(-2.f, acc[f*4+0], nf10 + c0x), 1e-12f);
            float s1 = fmaxf(fmaf(-2.f, acc[f*4+1], nf10 + c1x), 1e-12f);
            float s2 = fmaxf(fmaf(-2.f, acc[f*4+2], nf11 + c0x), 1e-12f);
            float s3 = fmaxf(fmaf(-2.f, acc[f*4+3], nf11 + c1x), 1e-12f);
            acc[f*4+0] = -100.f*sqrt_approx(s0);
            acc[f*4+1] = -100.f*sqrt_approx(s1);
            acc[f*4+2] = -100.f*sqrt_approx(s2);
            acc[f*4+3] = -100.f*sqrt_approx(s3);
            tm0 = fmaxf(tm0, fmaxf(acc[f*4+0], acc[f*4+1]));
            tm1 = fmaxf(tm1, fmaxf(acc[f*4+2], acc[f*4+3]));
        }
        float nm0 = fmaxf(rm0, tm0), nm1 = fmaxf(rm1, tm1);
        float sc0 = __expf(rm0 - nm0), sc1 = __expf(rm1 - nm1);
        rs0 *= sc0; rx0 *= sc0; ry0 *= sc0; rz0 *= sc0; rm0 = nm0;
        rs1 *= sc1; rx1 *= sc1; ry1 *= sc1; rz1 *= sc1; rm1 = nm1;
        #pragma unroll
        for (int f = 0; f < 8; f++){
            int n = f*8 + (lane & 3)*2;
            float4 c0 = *(const float4*)(cib + n*16);
            float4 c1 = *(const float4*)(cib + n*16 + 16);
            float w0 = __expf(acc[f*4+0] - nm0);
            float w1 = __expf(acc[f*4+1] - nm0);
            float w2 = __expf(acc[f*4+2] - nm1);
            float w3 = __expf(acc[f*4+3] - nm1);
            rs0 += w0 + w1; rs1 += w2 + w3;
            rx0 = fmaf(w0, c0.y, fmaf(w1, c1.y, rx0));
            ry0 = fmaf(w0, c0.z, fmaf(w1, c1.z, ry0));
            rz0 = fmaf(w0, c0.w, fmaf(w1, c1.w, rz0));
            rx1 = fmaf(w2, c0.y, fmaf(w3, c1.y, rx1));
            ry1 = fmaf(w2, c0.z, fmaf(w3, c1.z, ry1));
            rz1 = fmaf(w2, c0.w, fmaf(w3, c1.w, rz1));
        }
        bar_named(1 + grp);
    }

    #pragma unroll
    for (int o = 1; o <= 2; o <<= 1){
        float om = __shfl_xor_sync(0xffffffffu, rm0, o);
        float os = __shfl_xor_sync(0xffffffffu, rs0, o);
        float ox = __shfl_xor_sync(0xffffffffu, rx0, o);
        float oy = __shfl_xor_sync(0xffffffffu, ry0, o);
        float oz = __shfl_xor_sync(0xffffffffu, rz0, o);
        float nm = fmaxf(rm0, om);
        float e1 = __expf(rm0 - nm), e2 = __expf(om - nm);
        rs0 = rs0*e1 + os*e2; rx0 = rx0*e1 + ox*e2;
        ry0 = ry0*e1 + oy*e2; rz0 = rz0*e1 + oz*e2; rm0 = nm;
        om = __shfl_xor_sync(0xffffffffu, rm1, o);
        os = __shfl_xor_sync(0xffffffffu, rs1, o);
        ox = __shfl_xor_sync(0xffffffffu, rx1, o);
        oy = __shfl_xor_sync(0xffffffffu, ry1, o);
        oz = __shfl_xor_sync(0xffffffffu, rz1, o);
        nm = fmaxf(rm1, om);
        e1 = __expf(rm1 - nm); e2 = __expf(om - nm);
        rs1 = rs1*e1 + os*e2; rx1 = rx1*e1 + ox*e2;
        ry1 = ry1*e1 + oy*e2; rz1 = rz1*e1 + oz*e2; rm1 = nm;
    }

    __syncthreads();
    float* mg = (float*)(smem + MG_SM);
    int rl0 = gwid*16 + (lane >> 2);
    if (grp == 1 && (lane & 3) == 0){
        mg[rl0*5+0] = rm0; mg[rl0*5+1] = rs0; mg[rl0*5+2] = rx0; mg[rl0*5+3] = ry0; mg[rl0*5+4] = rz0;
        mg[(rl0+8)*5+0] = rm1; mg[(rl0+8)*5+1] = rs1; mg[(rl0+8)*5+2] = rx1; mg[(rl0+8)*5+3] = ry1; mg[(rl0+8)*5+4] = rz1;
    }
    __syncthreads();
    if (grp == 0 && (lane & 3) == 0){
        float m2 = mg[rl0*5+0], s2 = mg[rl0*5+1], x2 = mg[rl0*5+2], y2 = mg[rl0*5+3], z2 = mg[rl0*5+4];
        float nm = fmaxf(rm0, m2);
        float e1 = __expf(rm0 - nm), e2 = __expf(m2 - nm);
        float S = rs0*e1 + s2*e2, X = rx0*e1 + x2*e2, Y = ry0*e1 + y2*e2, Z = rz0*e1 + z2*e2;
        int n = n0 + rl0;
        if (n < NPTS){
            size_t pi = (bofs + n)*NSPLIT + split;
            g_pm[pi] = nm; g_ps[pi] = S; g_px[pi] = X; g_py[pi] = Y; g_pz[pi] = Z;
        }
        m2 = mg[(rl0+8)*5+0]; s2 = mg[(rl0+8)*5+1]; x2 = mg[(rl0+8)*5+2]; y2 = mg[(rl0+8)*5+3]; z2 = mg[(rl0+8)*5+4];
        nm = fmaxf(rm1, m2);
        e1 = __expf(rm1 - nm); e2 = __expf(m2 - nm);
        S = rs1*e1 + s2*e2; X = rx1*e1 + x2*e2; Y = ry1*e1 + y2*e2; Z = rz1*e1 + z2*e2;
        n = n0 + rl0 + 8;
        if (n < NPTS){
            size_t pi = (bofs + n)*NSPLIT + split;
            g_pm[pi] = nm; g_ps[pi] = S; g_px[pi] = X; g_py[pi] = Y; g_pz[pi] = Z;
        }
    }
}

// ---------------- K3: split-merge + self_rec (expansion form) ----------------
__global__ void __launch_bounds__(256) k3_selfrec(const float* __restrict__ verts2){
    __shared__ __align__(16) float sx[K3CH+4];
    __shared__ __align__(16) float sy[K3CH+4];
    __shared__ __align__(16) float sz[K3CH+4];
    __shared__ __align__(16) float sq[K3CH+4];
    int b = blockIdx.y;
    int part = threadIdx.x & 3;
    int nl = threadIdx.x >> 2;
    int n = blockIdx.x*64 + nl;
    bool valid = n < NPTS;
    size_t bofs = (size_t)b*NPTS;
    float vx=0.f, vy=0.f, vz=0.f;
    if (valid){
        float m = -1e30f, s = 0.f, x = 0.f, y = 0.f, z = 0.f;
        #pragma unroll
        for (int sp = 0; sp < NSPLIT; sp++){
            size_t pi = (bofs + n)*NSPLIT + sp;
            float m2 = g_pm[pi], s2 = g_ps[pi], x2 = g_px[pi], y2 = g_py[pi], z2 = g_pz[pi];
            float nm = fmaxf(m, m2);
            float a1 = __expf(m - nm), a2 = __expf(m2 - nm);
            s = s*a1 + s2*a2; x = x*a1 + x2*a2; y = y*a1 + y2*a2; z = z*a1 + z2*a2;
            m = nm;
        }
        float inv = 1.f / s;
        vx = x*inv; vy = y*inv; vz = z*inv;
        if (part == 0){
            g_verts12[(bofs + n)*3 + 0] = vx;
            g_verts12[(bofs + n)*3 + 1] = vy;
            g_verts12[(bofs + n)*3 + 2] = vz;
        }
    }
    float np = fmaf(vx,vx, fmaf(vy,vy, vz*vz));
    float m2x = -2.f*vx, m2y = -2.f*vy, m2z = -2.f*vz;
    const float* v2 = verts2 + bofs*3;
    float best = 3.4e38f;
    for (int m0 = 0; m0 < NPTS; m0 += K3CH){
        int cnt = min(K3CH, NPTS - m0);
        __syncthreads();
        for (int i = threadIdx.x; i < cnt; i += 256){
            float qx = v2[(m0+i)*3], qy = v2[(m0+i)*3+1], qz = v2[(m0+i)*3+2];
            sx[i] = qx; sy[i] = qy; sz[i] = qz;
            sq[i] = fmaf(qx,qx, fmaf(qy,qy, qz*qz));
        }
        if (threadIdx.x < 4){
            sx[cnt+threadIdx.x] = 0.f; sy[cnt+threadIdx.x] = 0.f; sz[cnt+threadIdx.x] = 0.f;
            sq[cnt+threadIdx.x] = 1e30f;
        }
        __syncthreads();
        int ng = (cnt + 3) >> 2;
        for (int g = part; g < ng; g += 4){
            float4 X = *(const float4*)(sx + 4*g);
            float4 Y = *(const float4*)(sy + 4*g);
            float4 Z = *(const float4*)(sz + 4*g);
            float4 Q = *(const float4*)(sq + 4*g);
            float t0 = fmaf(m2x, X.x, Q.x); t0 = fmaf(m2y, Y.x, t0); t0 = fmaf(m2z, Z.x, t0);
            float t1 = fmaf(m2x, X.y, Q.y); t1 = fmaf(m2y, Y.y, t1); t1 = fmaf(m2z, Z.y, t1);
            float t2 = fmaf(m2x, X.z, Q.z); t2 = fmaf(m2y, Y.z, t2); t2 = fmaf(m2z, Z.z, t2);
            float t3 = fmaf(m2x, X.w, Q.w); t3 = fmaf(m2y, Y.w, t3); t3 = fmaf(m2z, Z.w, t3);
            best = fminf(best, fminf(fminf(t0,t1), fminf(t2,t3)));
        }
    }
    best = fminf(best, __shfl_xor_sync(0xffffffffu, best, 1));
    best = fminf(best, __shfl_xor_sync(0xffffffffu, best, 2));
    float contrib = (part == 0 && valid) ? (best + np) : 0.f;
    __syncthreads();
    block_sum_atomic(contrib, &g_self_sum);
}

// ---------------- K4: top-10 nearest neighbors (expansion form) ----------------
__global__ void __launch_bounds__(256) k4_topk(const float* __restrict__ verts1){
    __shared__ __align__(16) float sx[K3CH+4];
    __shared__ __align__(16) float sy[K3CH+4];
    __shared__ __align__(16) float sz[K3CH+4];
    __shared__ __align__(16) float sq[K3CH+4];
    __shared__ float smval[256][10];
    __shared__ int   smidx[256][10];
    int b = blockIdx.y;
    int part = threadIdx.x & 3;
    int nl = threadIdx.x >> 2;
    int n = blockIdx.x*64 + nl;
    const float* v1 = verts1 + (size_t)b*NPTS*3;
    float vx=0.f, vy=0.f, vz=0.f;
    if (n < NPTS){ vx = v1[3*n]; vy = v1[3*n+1]; vz = v1[3*n+2]; }
    float m2x = -2.f*vx, m2y = -2.f*vy, m2z = -2.f*vz;
    float val[10]; int idx[10];
    #pragma unroll
    for (int q = 0; q < 10; q++){ val[q] = 3.4e38f; idx[q] = 0; }
    for (int m0 = 0; m0 < NPTS; m0 += K3CH){
        int cnt = min(K3CH, NPTS - m0);
        __syncthreads();
        for (int i = threadIdx.x; i < cnt; i += 256){
            float qx = v1[(m0+i)*3], qy = v1[(m0+i)*3+1], qz = v1[(m0+i)*3+2];
            sx[i] = qx; sy[i] = qy; sz[i] = qz;
            sq[i] = fmaf(qx,qx, fmaf(qy,qy, qz*qz));
        }
        if (threadIdx.x < 4){
            sx[cnt+threadIdx.x] = 0.f; sy[cnt+threadIdx.x] = 0.f; sz[cnt+threadIdx.x] = 0.f;
            sq[cnt+threadIdx.x] = 1e30f;
        }
        __syncthreads();
        int ng = (cnt + 3) >> 2;
        for (int g = part; g < ng; g += 4){
            float4 X = *(const float4*)(sx + 4*g);
            float4 Y = *(const float4*)(sy + 4*g);
            float4 Z = *(const float4*)(sz + 4*g);
            float4 Q = *(const float4*)(sq + 4*g);
            float t0 = fmaf(m2x, X.x, Q.x); t0 = fmaf(m2y, Y.x, t0); t0 = fmaf(m2z, Z.x, t0);
            float t1 = fmaf(m2x, X.y, Q.y); t1 = fmaf(m2y, Y.y, t1); t1 = fmaf(m2z, Z.y, t1);
            float t2 = fmaf(m2x, X.z, Q.z); t2 = fmaf(m2y, Y.z, t2); t2 = fmaf(m2z, Z.z, t2);
            float t3 = fmaf(m2x, X.w, Q.w); t3 = fmaf(m2y, Y.w, t3); t3 = fmaf(m2z, Z.w, t3);
            float gm = fminf(fminf(t0,t1), fminf(t2,t3));
            if (gm < val[9]){
                float ds[4]; ds[0]=t0; ds[1]=t1; ds[2]=t2; ds[3]=t3;
                #pragma unroll
                for (int k = 0; k < 4; k++){
                    if (ds[k] < val[9]){
                        float cv = ds[k]; int ci = m0 + 4*g + k;
                        #pragma unroll
                        for (int q = 0; q < 10; q++){
                            if (cv < val[q]){
                                float tv = val[q]; int ti = idx[q];
                                val[q] = cv; idx[q] = ci; cv = tv; ci = ti;
                            }
                        }
                    }
                }
            }
        }
    }
    #pragma unroll
    for (int q = 0; q < 10; q++){ smval[threadIdx.x][q] = val[q]; smidx[threadIdx.x][q] = idx[q]; }
    __syncthreads();
    if (part == 0 && n < NPTS){
        int h0=0,h1=0,h2=0,h3=0;
        int base = threadIdx.x;
        int out = (b*NPTS + n)*KNN;
        #pragma unroll
        for (int q = 0; q < 10; q++){
            float b0 = smval[base][h0],   b1 = smval[base+1][h1];
            float b2 = smval[base+2][h2], b3 = smval[base+3][h3];
            float mm = fminf(fminf(b0,b1), fminf(b2,b3));
            int chosen;
            if (mm == b0){ chosen = smidx[base][h0];   h0++; }
            else if (mm == b1){ chosen = smidx[base+1][h1]; h1++; }
            else if (mm == b2){ chosen = smidx[base+2][h2]; h2++; }
            else { chosen = smidx[base+3][h3]; h3++; }
            g_idx11[out + q] = chosen;
        }
    }
}

// ---------------- K5: deform feature MSE (warp-per-point) ----------------
__global__ void __launch_bounds__(256) k5_deform(const float* __restrict__ feat1){
    int w = threadIdx.x >> 5, lane = threadIdx.x & 31;
    int base = blockIdx.x*64 + w*8;
    float acc = 0.f;
    #pragma unroll
    for (int p = 0; p < 8; p++){
        int bn = base + p;
        if (bn < BATCH*NPTS){
            int b = bn / NPTS, n = bn - b*NPTS;
            const float* f1 = feat1 + (size_t)b*NPTS*CDIM;
            float4 fc = *(const float4*)(f1 + (size_t)n*CDIM + lane*4);
            #pragma unroll
            for (int q = 0; q < KNN; q++){
                int m = g_idx11[bn*KNN + q];
                float4 fm = *(const float4*)(f1 + (size_t)m*CDIM + lane*4);
                float d0 = fm.x - fc.x, d1 = fm.y - fc.y;
                float d2 = fm.z - fc.z, d3 = fm.w - fc.w;
                acc = fmaf(d0,d0, acc); acc = fmaf(d1,d1, acc);
                acc = fmaf(d2,d2, acc); acc = fmaf(d3,d3, acc);
            }
        }
    }
    block_sum_atomic(acc, &g_deform_sum);
}

// ---------------- K_mm: per-(tensor,b) minmax + grid-index minmax ----------------
__global__ void __launch_bounds__(1024) k_mm(const float* __restrict__ verts2){
    __shared__ float rf[32][4];
    __shared__ int ri[32][4];
    __shared__ float bc[4];
    int bx = blockIdx.x;
    int tensor = bx >> 2, b = bx & 3;
    size_t bofs = (size_t)b*NPTS;
    const float* p = tensor ? (verts2 + bofs*3) : (g_verts12 + bofs*3);
    int tid = threadIdx.x, lane = tid & 31, w = tid >> 5;

    float mnx = 1e30f, mny = 1e30f, mxx = -1e30f, mxy = -1e30f;
    for (int i = tid; i < NPTS; i += 1024){
        float x = p[3*i], y = p[3*i+1];
        mnx = fminf(mnx, x); mny = fminf(mny, y);
        mxx = fmaxf(mxx, x); mxy = fmaxf(mxy, y);
    }
    #pragma unroll
    for (int o = 16; o; o >>= 1){
        mnx = fminf(mnx, __shfl_xor_sync(0xffffffffu, mnx, o));
        mny = fminf(mny, __shfl_xor_sync(0xffffffffu, mny, o));
        mxx = fmaxf(mxx, __shfl_xor_sync(0xffffffffu, mxx, o));
        mxy = fmaxf(mxy, __shfl_xor_sync(0xffffffffu, mxy, o));
    }
    if (!lane){ rf[w][0] = mnx; rf[w][1] = mny; rf[w][2] = mxx; rf[w][3] = mxy; }
    __syncthreads();
    if (w == 0){
        mnx = rf[lane][0]; mny = rf[lane][1]; mxx = rf[lane][2]; mxy = rf[lane][3];
        #pragma unroll
        for (int o = 16; o; o >>= 1){
            mnx = fminf(mnx, __shfl_xor_sync(0xffffffffu, mnx, o));
            mny = fminf(mny, __shfl_xor_sync(0xffffffffu, mny, o));
            mxx = fmaxf(mxx, __shfl_xor_sync(0xffffffffu, mxx, o));
            mxy = fmaxf(mxy, __shfl_xor_sync(0xffffffffu, mxy, o));
        }
        if (!lane){
            bc[0] = mnx; bc[1] = mny; bc[2] = mxx; bc[3] = mxy;
            g_mmf[tensor][b][0] = mnx; g_mmf[tensor][b][1] = mny;
            g_mmf[tensor][b][2] = mxx; g_mmf[tensor][b][3] = mxy;
        }
    }
    __syncthreads();
    float minx = bc[0], miny = bc[1], maxx = bc[2], maxy = bc[3];
    float gs = __fdiv_rn(fmaxf(maxx - minx, maxy - miny), 221.0f);

    int imnx = 0x7FFFFFFF, imny = 0x7FFFFFFF;
    int imxx = (int)0x80000000, imxy = (int)0x80000000;
    for (int i = tid; i < NPTS; i += 1024){
        int ix = (int)floorf(__fdiv_rn(p[3*i]   - minx, gs));
        int iy = (int)floorf(__fdiv_rn(p[3*i+1] - miny, gs));
        imnx = min(imnx, ix); imny = min(imny, iy);
        imxx = max(imxx, ix); imxy = max(imxy, iy);
    }
    #pragma unroll
    for (int o = 16; o; o >>= 1){
        imnx = min(imnx, __shfl_xor_sync(0xffffffffu, imnx, o));
        imny = min(imny, __shfl_xor_sync(0xffffffffu, imny, o));
        imxx = max(imxx, __shfl_xor_sync(0xffffffffu, imxx, o));
        imxy = max(imxy, __shfl_xor_sync(0xffffffffu, imxy, o));
    }
    if (!lane){ ri[w][0] = imnx; ri[w][1] = imny; ri[w][2] = imxx; ri[w][3] = imxy; }
    __syncthreads();
    if (w == 0){
        imnx = ri[lane][0]; imny = ri[lane][1]; imxx = ri[lane][2]; imxy = ri[lane][3];
        #pragma unroll
        for (int o = 16; o; o >>= 1){
            imnx = min(imnx, __shfl_xor_sync(0xffffffffu, imnx, o));
            imny = min(imny, __shfl_xor_sync(0xffffffffu, imny, o));
            imxx = max(imxx, __shfl_xor_sync(0xffffffffu, imxx, o));
            imxy = max(imxy, __shfl_xor_sync(0xffffffffu, imxy, o));
        }
        if (!lane){
            g_oxy[tensor][b][0] = 111 - ((imxx + imnx + 2) >> 1);
            g_oxy[tensor][b][1] = 111 - ((imxy + imny + 2) >> 1);
        }
    }
}

// ---------------- K8: scatter z into images ----------------
__global__ void __launch_bounds__(256) k8_scatter(const float* __restrict__ verts2){
    int tb = blockIdx.y;
    int tensor = tb >> 2, b = tb & 3;
    const float* p = tensor ? (verts2 + (size_t)b*NPTS*3) : (g_verts12 + (size_t)b*NPTS*3);
    int i = blockIdx.x*256 + threadIdx.x;
    if (i >= NPTS) return;
    float minx = g_mmf[tensor][b][0];
    float miny = g_mmf[tensor][b][1];
    float maxx = g_mmf[tensor][b][2];
    float maxy = g_mmf[tensor][b][3];
    float gs = __fdiv_rn(fmaxf(maxx - minx, maxy - miny), 221.0f);
    int ix = (int)floorf(__fdiv_rn(p[3*i]   - minx, gs));
    int iy = (int)floorf(__fdiv_rn(p[3*i+1] - miny, gs));
    float z = p[3*i+2];
    int ox = g_oxy[tensor][b][0], oy = g_oxy[tensor][b][1];
    float* img = g_img[tensor] + b*IMGSZ;
    #pragma unroll
    for (int t2 = 0; t2 < 25; t2++){
        int du = t2 / 5;
        int dv = t2 - du*5;
        int uu = ix + du - 1 + ox;
        int vv = iy + dv - 1 + oy;
        uu += (uu < 0) - (uu > IMG-1);
        vv += (vv < 0) - (vv > IMG-1);
        uu = max(0, min(IMG-1, uu));
        vv = max(0, min(IMG-1, vv));
        atomicAdd(&img[uu*IMG + vv], z);
    }
}

// ---------------- K9: image MSE ----------------
__global__ void __launch_bounds__(256) k9_imgloss(){
    int i = blockIdx.x*256 + threadIdx.x;
    float d = 0.f;
    if (i < BATCH*IMGSZ){
        float a = g_img[0][i], b2 = g_img[1][i];
        float s1 = 1.f/(1.f + __expf(-a));
        float s2 = 1.f/(1.f + __expf(-b2));
        float df = s1 - s2;
        d = df*df;
    }
    block_sum_atomic(d, &g_img_sum);
}

// ---------------- K10: finalize ----------------
__global__ void k10_final(float* out){
    if (threadIdx.x == 0 && blockIdx.x == 0){
        double self_l = g_self_sum / (double)(BATCH*NPTS);
        double def_l  = g_deform_sum / ((double)BATCH*NPTS*KNN*CDIM);
        double img_l  = g_img_sum / ((double)BATCH*IMGSZ);
        out[0] = (float)(self_l + img_l + def_l);
    }
}

// ---------------- launch ----------------
extern "C" void kernel_launch(void* const* d_in, const int* in_sizes, int n_in,
                              void* d_out, int out_size){
    const float* verts1 = (const float*)d_in[0];
    const float* verts2 = (const float*)d_in[1];
    const float* feat1  = (const float*)d_in[2];
    const float* feat2  = (const float*)d_in[3];
    float* out = (float*)d_out;

    cudaFuncSetAttribute(k2_softmax_mma, cudaFuncAttributeMaxDynamicSharedMemorySize, K2SMEM);

    k_pre<<<4995, 256>>>(feat1, feat2);
    k2_softmax_mma<<<dim3(MTILES, NSPLIT, BATCH), K2_THREADS, K2SMEM>>>(verts2);
    k3_selfrec<<<dim3((NPTS+63)/64, BATCH), 256>>>(verts2);
    k4_topk<<<dim3((NPTS+63)/64, BATCH), 256>>>(verts1);
    k5_deform<<<(BATCH*NPTS + 63)/64, 256>>>(feat1);
    k_mm<<<8, 1024>>>(verts2);
    k8_scatter<<<dim3((NPTS+255)/256, 2*BATCH), 256>>>(verts2);
    k9_imgloss<<<(BATCH*IMGSZ+255)/256, 256>>>();
    k10_final<<<1, 32>>>(out);
}

// round 13
// speedup vs baseline: 1.1369x; 1.0457x over previous
#include <cuda_runtime.h>
#include <cuda_bf16.h>
#include <cstdint>
#include <math.h>

typedef unsigned int u32;
typedef unsigned long long u64;

#define BATCH 4
#define NPTS 4995
#define CDIM 128
#define KNN 10
#define IMG 224
#define IMGSZ (IMG*IMG)

#define MT 128
#define MTILES 40
#define NSPLIT 8
#define CHUNK 640
#define K2_THREADS 512

// K2 smem layout (bytes)
#define BBUF 34816          // one 64-row B buffer: hi 17408 + lo 17408
#define BLO 17408
#define AH_SM 0
#define AL_SM 34816
#define BB_SM 69632         // 4 buffers x 34816 = 139264
#define CI_SM 208896        // 4 x 1024
#define MG_SM 212992        // 128 x 5 floats
#define K2SMEM 215552

#define K3CH 2048
#define K4CH 1024
#define K4PTS 32
#define K4THREADS 128

// ---------------- scratch ----------------
__device__ unsigned short g_f1hi[BATCH*NPTS*CDIM];
__device__ unsigned short g_f1lo[BATCH*NPTS*CDIM];
__device__ unsigned short g_f2hi[BATCH*NPTS*CDIM];
__device__ unsigned short g_f2lo[BATCH*NPTS*CDIM];
__device__ float g_nf1[BATCH*NPTS];
__device__ float g_nf2[BATCH*NPTS];
__device__ float g_pm[BATCH*NPTS*NSPLIT];
__device__ float g_ps[BATCH*NPTS*NSPLIT];
__device__ float g_px[BATCH*NPTS*NSPLIT];
__device__ float g_py[BATCH*NPTS*NSPLIT];
__device__ float g_pz[BATCH*NPTS*NSPLIT];
__device__ float g_verts12[BATCH*NPTS*3];
__device__ int   g_idx11[BATCH*NPTS*KNN];
__device__ float g_img[2][BATCH*IMGSZ];
__device__ float g_mmf[2][BATCH][4];   // minx,miny,maxx,maxy
__device__ int   g_oxy[2][BATCH][2];   // ox, oy
__device__ double g_self_sum;
__device__ double g_deform_sum;
__device__ double g_img_sum;

// ---------------- generic helpers ----------------
__device__ __forceinline__ float sqrt_approx(float x){
    float y; asm("sqrt.approx.f32 %0, %1;" : "=f"(y) : "f"(x)); return y;
}
__device__ __forceinline__ void block_sum_atomic(float v, double* target){
    __shared__ float red[32];
    int lane = threadIdx.x & 31, w = threadIdx.x >> 5;
    #pragma unroll
    for (int o = 16; o; o >>= 1) v += __shfl_xor_sync(0xffffffffu, v, o);
    if (!lane) red[w] = v;
    __syncthreads();
    if (w == 0){
        int nw = (blockDim.x + 31) >> 5;
        float s = (lane < nw) ? red[lane] : 0.f;
        #pragma unroll
        for (int o = 16; o; o >>= 1) s += __shfl_xor_sync(0xffffffffu, s, o);
        if (!lane) atomicAdd(target, (double)s);
    }
}
__device__ __forceinline__ u32 smem_u32(const void* p){
    u32 a;
    asm("{ .reg .u64 t; cvta.to.shared.u64 t, %1; cvt.u32.u64 %0, t; }" : "=r"(a) : "l"(p));
    return a;
}
__device__ __forceinline__ void bar_named(int id){
    asm volatile("bar.sync %0, 256;" :: "r"(id) : "memory");
}

// ---------------- mma.sync / ldmatrix wrappers ----------------
__device__ __forceinline__ void ldsm_x4(u32* r, u32 addr){
    asm volatile("ldmatrix.sync.aligned.m8n8.x4.shared.b16 {%0,%1,%2,%3}, [%4];"
        : "=r"(r[0]), "=r"(r[1]), "=r"(r[2]), "=r"(r[3]) : "r"(addr));
}
__device__ __forceinline__ void mma_bf16(float* d, const u32* a, u32 b0, u32 b1){
    asm volatile(
        "mma.sync.aligned.m16n8k16.row.col.f32.bf16.bf16.f32 "
        "{%0,%1,%2,%3}, {%4,%5,%6,%7}, {%8,%9}, {%0,%1,%2,%3};"
        : "+f"(d[0]), "+f"(d[1]), "+f"(d[2]), "+f"(d[3])
        : "r"(a[0]), "r"(a[1]), "r"(a[2]), "r"(a[3]), "r"(b0), "r"(b1));
}

// ---------------- K_pre: init + double-bf16 split + row norms ----------------
__global__ void __launch_bounds__(256) k_pre(const float* __restrict__ f1,
                                             const float* __restrict__ f2){
    int tid = threadIdx.x;
    int i = blockIdx.x*256 + tid;

    if (i < 2*BATCH*IMGSZ) ((float*)g_img)[i] = 0.0f;
    if (i == 0){ g_self_sum = 0.0; g_deform_sum = 0.0; g_img_sum = 0.0; }

    const int half = BATCH*NPTS*CDIM/4;
    if (i < 2*half){
        bool second = i >= half;
        int j = second ? i - half : i;
        float4 v = ((const float4*)(second ? f2 : f1))[j];
        unsigned short* hi = second ? g_f2hi : g_f1hi;
        unsigned short* lo = second ? g_f2lo : g_f1lo;
        float vv[4]; vv[0]=v.x; vv[1]=v.y; vv[2]=v.z; vv[3]=v.w;
        unsigned short hu[4], lu[4];
        #pragma unroll
        for (int c = 0; c < 4; c++){
            __nv_bfloat16 h = __float2bfloat16_rn(vv[c]);
            float r = vv[c] - __bfloat162float(h);
            __nv_bfloat16 l = __float2bfloat16_rn(r);
            hu[c] = __bfloat16_as_ushort(h);
            lu[c] = __bfloat16_as_ushort(l);
        }
        ((uint2*)hi)[j] = make_uint2((u32)hu[0] | ((u32)hu[1] << 16),
                                     (u32)hu[2] | ((u32)hu[3] << 16));
        ((uint2*)lo)[j] = make_uint2((u32)lu[0] | ((u32)lu[1] << 16),
                                     (u32)lu[2] | ((u32)lu[3] << 16));
    }

    int gw = i >> 5;
    int lane = tid & 31;
    if (gw < 2*BATCH*NPTS){
        const float* src; float* dst; int row;
        if (gw < BATCH*NPTS){ src = f1; dst = g_nf1; row = gw; }
        else { src = f2; dst = g_nf2; row = gw - BATCH*NPTS; }
        float4 v = *(const float4*)(src + (size_t)row*CDIM + lane*4);
        float s = v.x*v.x + v.y*v.y + v.z*v.z + v.w*v.w;
        #pragma unroll
        for (int o = 16; o; o >>= 1) s += __shfl_xor_sync(0xffffffffu, s, o);
        if (!lane) dst[row] = s;
    }
}

// ---------------- K2: HMMA fused softmax, two warp-groups pipelined ----------------
__global__ void __launch_bounds__(K2_THREADS)
k2_softmax_mma(const float* __restrict__ verts2){
    extern __shared__ char smem[];
    const int tid = threadIdx.x;
    const int wid = tid >> 5, lane = tid & 31;
    const int grp = wid >> 3;
    const int gwid = wid & 7;
    const int gtid = tid & 255;
    const int b = blockIdx.z, split = blockIdx.y, mt = blockIdx.x;
    const int n0 = mt * MT;
    const int cs = split * CHUNK;
    const int ce = min(cs + CHUNK, NPTS);
    const int T = (ce - cs + 63) >> 6;
    const int H = (T + 1) >> 1;
    const int tbase = grp ? H : 0;
    const int myT = grp ? (T - H) : H;
    const size_t bofs = (size_t)b * NPTS;
    const float* v2 = verts2 + bofs * 3;
    u32 sb = smem_u32(smem);

    for (int i = tid; i < 2048; i += K2_THREADS){
        int row = i >> 4, c8 = i & 15;
        int n = n0 + row;
        uint4 vh = make_uint4(0u,0u,0u,0u);
        uint4 vl = make_uint4(0u,0u,0u,0u);
        if (n < NPTS){
            vh = *(const uint4*)(g_f1hi + ((bofs + n) << 7) + (c8 << 3));
            vl = *(const uint4*)(g_f1lo + ((bofs + n) << 7) + (c8 << 3));
        }
        *(uint4*)(smem + AH_SM + row*272 + c8*16) = vh;
        *(uint4*)(smem + AL_SM + row*272 + c8*16) = vl;
    }
    if (myT > 0){
        int m0 = cs + tbase*64;
        char* bufb = smem + BB_SM + (grp*2 + 0)*BBUF;
        for (int i = gtid; i < 2048; i += 256){
            int row = i >> 5, c8 = i & 31;
            int m = m0 + row;
            uint4 v = make_uint4(0u,0u,0u,0u);
            const unsigned short* src = (c8 < 16) ? g_f2hi : g_f2lo;
            int cc8 = c8 & 15;
            if (m < ce) v = *(const uint4*)(src + ((bofs + m) << 7) + (cc8 << 3));
            *(uint4*)(bufb + ((c8 < 16) ? 0 : BLO) + row*272 + cc8*16) = v;
        }
        if (gtid < 64){
            int m = m0 + gtid;
            float4 ci;
            if (m < ce){ ci.x = g_nf2[bofs+m]; ci.y = v2[m*3]; ci.z = v2[m*3+1]; ci.w = v2[m*3+2]; }
            else { ci.x = 1e30f; ci.y = 0.f; ci.z = 0.f; ci.w = 0.f; }
            *(float4*)(smem + CI_SM + (grp*2 + 0)*1024 + gtid*16) = ci;
        }
    }
    __syncthreads();

    const u32 aRowOff = (u32)((gwid*16 + (lane & 15)) * 272 + (lane >> 4) * 16);
    const u32 aHa = sb + AH_SM + aRowOff;
    const u32 aLa = sb + AL_SM + aRowOff;
    const u32 bOff4 = (u32)(((lane & 7) + ((lane >> 4) << 3)) * 272 + (((lane >> 3) & 1) << 4));

    float nf10 = 0.f, nf11 = 0.f;
    const int r0g = n0 + gwid*16 + (lane >> 2);
    if (r0g < NPTS) nf10 = g_nf1[bofs + r0g];
    if (r0g + 8 < NPTS) nf11 = g_nf1[bofs + r0g + 8];

    float rm0=-1e30f, rs0=0.f, rx0=0.f, ry0=0.f, rz0=0.f;
    float rm1=-1e30f, rs1=0.f, rx1=0.f, ry1=0.f, rz1=0.f;

    for (int j = 0; j < myT; j++){
        if (j + 1 < myT){
            int m0 = cs + (tbase + j + 1)*64;
            int nb = (j + 1) & 1;
            char* bufb = smem + BB_SM + (grp*2 + nb)*BBUF;
            for (int i = gtid; i < 2048; i += 256){
                int row = i >> 5, c8 = i & 31;
                int m = m0 + row;
                uint4 v = make_uint4(0u,0u,0u,0u);
                const unsigned short* src = (c8 < 16) ? g_f2hi : g_f2lo;
                int cc8 = c8 & 15;
                if (m < ce) v = *(const uint4*)(src + ((bofs + m) << 7) + (cc8 << 3));
                *(uint4*)(bufb + ((c8 < 16) ? 0 : BLO) + row*272 + cc8*16) = v;
            }
            if (gtid < 64){
                int m = m0 + gtid;
                float4 ci;
                if (m < ce){ ci.x = g_nf2[bofs+m]; ci.y = v2[m*3]; ci.z = v2[m*3+1]; ci.w = v2[m*3+2]; }
                else { ci.x = 1e30f; ci.y = 0.f; ci.z = 0.f; ci.w = 0.f; }
                *(float4*)(smem + CI_SM + (grp*2 + nb)*1024 + gtid*16) = ci;
            }
        }

        float acc[32];
        #pragma unroll
        for (int i = 0; i < 32; i++) acc[i] = 0.f;
        const u32 bBase = sb + BB_SM + (u32)((grp*2 + (j & 1))*BBUF) + bOff4;
        #pragma unroll
        for (int ks = 0; ks < 8; ks++){
            u32 ah[4], al[4];
            ldsm_x4(ah, aHa + ks*32);
            ldsm_x4(al, aLa + ks*32);
            #pragma unroll
            for (int fp = 0; fp < 4; fp++){
                u32 bh[4], bl[4];
                u32 baddr = bBase + (u32)(fp*4352 + ks*32);
                ldsm_x4(bh, baddr);
                ldsm_x4(bl, baddr + BLO);
                mma_bf16(acc + fp*8,     ah, bh[0], bh[1]);
                mma_bf16(acc + fp*8,     ah, bl[0], bl[1]);
                mma_bf16(acc + fp*8,     al, bh[0], bh[1]);
                mma_bf16(acc + fp*8 + 4, ah, bh[2], bh[3]);
                mma_bf16(acc + fp*8 + 4, ah, bl[2], bl[3]);
                mma_bf16(acc + fp*8 + 4, al, bh[2], bh[3]);
            }
        }

        const char* cib = smem + CI_SM + (grp*2 + (j & 1))*1024;
        float tm0 = -1e30f, tm1 = -1e30f;
        #pragma unroll
        for (int f = 0; f < 8; f++){
            int n = f*8 + (lane & 3)*2;
            float c0x = *(const float*)(cib + n*16);
            float c1x = *(const float*)(cib + n*16 + 16);
            float s0 = fmaxf(fmaf(-2.f, acc[f*4+0], nf10 + c0x), 1e-12f);
            float s1 = fmaxf(fmaf(-2.f, acc[f*4+1], nf10 + c1x), 1e-12f);
            float s2 = fmaxf(fmaf(-2.f, acc[f*4+2], nf11 + c0x), 1e-12f);
            float s3 = fmaxf(fmaf(-2.f, acc[f*4+3], nf11 + c1x), 1e-12f);
            acc[f*4+0] = -100.f*sqrt_approx(s0);
            acc[f*4+1] = -100.f*sqrt_approx(s1);
            acc[f*4+2] = -100.f*sqrt_approx(s2);
            acc[f*4+3] = -100.f*sqrt_approx(s3);
            tm0 = fmaxf(tm0, fmaxf(acc[f*4+0], acc[f*4+1]));
            tm1 = fmaxf(tm1, fmaxf(acc[f*4+2], acc[f*4+3]));
        }
        float nm0 = fmaxf(rm0, tm0), nm1 = fmaxf(rm1, tm1);
        float sc0 = __expf(rm0 - nm0), sc1 = __expf(rm1 - nm1);
        rs0 *= sc0; rx0 *= sc0; ry0 *= sc0; rz0 *= sc0; rm0 = nm0;
        rs1 *= sc1; rx1 *= sc1; ry1 *= sc1; rz1 *= sc1; rm1 = nm1;
        #pragma unroll
        for (int f = 0; f < 8; f++){
            int n = f*8 + (lane & 3)*2;
            float4 c0 = *(const float4*)(cib + n*16);
            float4 c1 = *(const float4*)(cib + n*16 + 16);
            float w0 = __expf(acc[f*4+0] - nm0);
            float w1 = __expf(acc[f*4+1] - nm0);
            float w2 = __expf(acc[f*4+2] - nm1);
            float w3 = __expf(acc[f*4+3] - nm1);
            rs0 += w0 + w1; rs1 += w2 + w3;
            rx0 = fmaf(w0, c0.y, fmaf(w1, c1.y, rx0));
            ry0 = fmaf(w0, c0.z, fmaf(w1, c1.z, ry0));
            rz0 = fmaf(w0, c0.w, fmaf(w1, c1.w, rz0));
            rx1 = fmaf(w2, c0.y, fmaf(w3, c1.y, rx1));
            ry1 = fmaf(w2, c0.z, fmaf(w3, c1.z, ry1));
            rz1 = fmaf(w2, c0.w, fmaf(w3, c1.w, rz1));
        }
        bar_named(1 + grp);
    }

    #pragma unroll
    for (int o = 1; o <= 2; o <<= 1){
        float om = __shfl_xor_sync(0xffffffffu, rm0, o);
        float os = __shfl_xor_sync(0xffffffffu, rs0, o);
        float ox = __shfl_xor_sync(0xffffffffu, rx0, o);
        float oy = __shfl_xor_sync(0xffffffffu, ry0, o);
        float oz = __shfl_xor_sync(0xffffffffu, rz0, o);
        float nm = fmaxf(rm0, om);
        float e1 = __expf(rm0 - nm), e2 = __expf(om - nm);
        rs0 = rs0*e1 + os*e2; rx0 = rx0*e1 + ox*e2;
        ry0 = ry0*e1 + oy*e2; rz0 = rz0*e1 + oz*e2; rm0 = nm;
        om = __shfl_xor_sync(0xffffffffu, rm1, o);
        os = __shfl_xor_sync(0xffffffffu, rs1, o);
        ox = __shfl_xor_sync(0xffffffffu, rx1, o);
        oy = __shfl_xor_sync(0xffffffffu, ry1, o);
        oz = __shfl_xor_sync(0xffffffffu, rz1, o);
        nm = fmaxf(rm1, om);
        e1 = __expf(rm1 - nm); e2 = __expf(om - nm);
        rs1 = rs1*e1 + os*e2; rx1 = rx1*e1 + ox*e2;
        ry1 = ry1*e1 + oy*e2; rz1 = rz1*e1 + oz*e2; rm1 = nm;
    }

    __syncthreads();
    float* mg = (float*)(smem + MG_SM);
    int rl0 = gwid*16 + (lane >> 2);
    if (grp == 1 && (lane & 3) == 0){
        mg[rl0*5+0] = rm0; mg[rl0*5+1] = rs0; mg[rl0*5+2] = rx0; mg[rl0*5+3] = ry0; mg[rl0*5+4] = rz0;
        mg[(rl0+8)*5+0] = rm1; mg[(rl0+8)*5+1] = rs1; mg[(rl0+8)*5+2] = rx1; mg[(rl0+8)*5+3] = ry1; mg[(rl0+8)*5+4] = rz1;
    }
    __syncthreads();
    if (grp == 0 && (lane & 3) == 0){
        float m2 = mg[rl0*5+0], s2 = mg[rl0*5+1], x2 = mg[rl0*5+2], y2 = mg[rl0*5+3], z2 = mg[rl0*5+4];
        float nm = fmaxf(rm0, m2);
        float e1 = __expf(rm0 - nm), e2 = __expf(m2 - nm);
        float S = rs0*e1 + s2*e2, X = rx0*e1 + x2*e2, Y = ry0*e1 + y2*e2, Z = rz0*e1 + z2*e2;
        int n = n0 + rl0;
        if (n < NPTS){
            size_t pi = (bofs + n)*NSPLIT + split;
            g_pm[pi] = nm; g_ps[pi] = S; g_px[pi] = X; g_py[pi] = Y; g_pz[pi] = Z;
        }
        m2 = mg[(rl0+8)*5+0]; s2 = mg[(rl0+8)*5+1]; x2 = mg[(rl0+8)*5+2]; y2 = mg[(rl0+8)*5+3]; z2 = mg[(rl0+8)*5+4];
        nm = fmaxf(rm1, m2);
        e1 = __expf(rm1 - nm); e2 = __expf(m2 - nm);
        S = rs1*e1 + s2*e2; X = rx1*e1 + x2*e2; Y = ry1*e1 + y2*e2; Z = rz1*e1 + z2*e2;
        n = n0 + rl0 + 8;
        if (n < NPTS){
            size_t pi = (bofs + n)*NSPLIT + split;
            g_pm[pi] = nm; g_ps[pi] = S; g_px[pi] = X; g_py[pi] = Y; g_pz[pi] = Z;
        }
    }
}

// ---------------- K3: split-merge + self_rec (expansion form) ----------------
__global__ void __launch_bounds__(256) k3_selfrec(const float* __restrict__ verts2){
    __shared__ __align__(16) float sx[K3CH+4];
    __shared__ __align__(16) float sy[K3CH+4];
    __shared__ __align__(16) float sz[K3CH+4];
    __shared__ __align__(16) float sq[K3CH+4];
    int b = blockIdx.y;
    int part = threadIdx.x & 3;
    int nl = threadIdx.x >> 2;
    int n = blockIdx.x*64 + nl;
    bool valid = n < NPTS;
    size_t bofs = (size_t)b*NPTS;
    float vx=0.f, vy=0.f, vz=0.f;
    if (valid){
        float m = -1e30f, s = 0.f, x = 0.f, y = 0.f, z = 0.f;
        #pragma unroll
        for (int sp = 0; sp < NSPLIT; sp++){
            size_t pi = (bofs + n)*NSPLIT + sp;
            float m2 = g_pm[pi], s2 = g_ps[pi], x2 = g_px[pi], y2 = g_py[pi], z2 = g_pz[pi];
            float nm = fmaxf(m, m2);
            float a1 = __expf(m - nm), a2 = __expf(m2 - nm);
            s = s*a1 + s2*a2; x = x*a1 + x2*a2; y = y*a1 + y2*a2; z = z*a1 + z2*a2;
            m = nm;
        }
        float inv = 1.f / s;
        vx = x*inv; vy = y*inv; vz = z*inv;
        if (part == 0){
            g_verts12[(bofs + n)*3 + 0] = vx;
            g_verts12[(bofs + n)*3 + 1] = vy;
            g_verts12[(bofs + n)*3 + 2] = vz;
        }
    }
    float np = fmaf(vx,vx, fmaf(vy,vy, vz*vz));
    float m2x = -2.f*vx, m2y = -2.f*vy, m2z = -2.f*vz;
    const float* v2 = verts2 + bofs*3;
    float best = 3.4e38f;
    for (int m0 = 0; m0 < NPTS; m0 += K3CH){
        int cnt = min(K3CH, NPTS - m0);
        __syncthreads();
        for (int i = threadIdx.x; i < cnt; i += 256){
            float qx = v2[(m0+i)*3], qy = v2[(m0+i)*3+1], qz = v2[(m0+i)*3+2];
            sx[i] = qx; sy[i] = qy; sz[i] = qz;
            sq[i] = fmaf(qx,qx, fmaf(qy,qy, qz*qz));
        }
        if (threadIdx.x < 4){
            sx[cnt+threadIdx.x] = 0.f; sy[cnt+threadIdx.x] = 0.f; sz[cnt+threadIdx.x] = 0.f;
            sq[cnt+threadIdx.x] = 1e30f;
        }
        __syncthreads();
        int ng = (cnt + 3) >> 2;
        for (int g = part; g < ng; g += 4){
            float4 X = *(const float4*)(sx + 4*g);
            float4 Y = *(const float4*)(sy + 4*g);
            float4 Z = *(const float4*)(sz + 4*g);
            float4 Q = *(const float4*)(sq + 4*g);
            float t0 = fmaf(m2x, X.x, Q.x); t0 = fmaf(m2y, Y.x, t0); t0 = fmaf(m2z, Z.x, t0);
            float t1 = fmaf(m2x, X.y, Q.y); t1 = fmaf(m2y, Y.y, t1); t1 = fmaf(m2z, Z.y, t1);
            float t2 = fmaf(m2x, X.z, Q.z); t2 = fmaf(m2y, Y.z, t2); t2 = fmaf(m2z, Z.z, t2);
            float t3 = fmaf(m2x, X.w, Q.w); t3 = fmaf(m2y, Y.w, t3); t3 = fmaf(m2z, Z.w, t3);
            best = fminf(best, fminf(fminf(t0,t1), fminf(t2,t3)));
        }
    }
    best = fminf(best, __shfl_xor_sync(0xffffffffu, best, 1));
    best = fminf(best, __shfl_xor_sync(0xffffffffu, best, 2));
    float contrib = (part == 0 && valid) ? (best + np) : 0.f;
    __syncthreads();
    block_sum_atomic(contrib, &g_self_sum);
}

// ---------------- K4: top-10 nearest neighbors (32 pts / 128 thr per block) ----------------
__global__ void __launch_bounds__(K4THREADS) k4_topk(const float* __restrict__ verts1){
    __shared__ __align__(16) float sx[K4CH+4];
    __shared__ __align__(16) float sy[K4CH+4];
    __shared__ __align__(16) float sz[K4CH+4];
    __shared__ __align__(16) float sq[K4CH+4];
    __shared__ float smval[K4THREADS][10];
    __shared__ int   smidx[K4THREADS][10];
    int b = blockIdx.y;
    int part = threadIdx.x & 3;
    int nl = threadIdx.x >> 2;
    int n = blockIdx.x*K4PTS + nl;
    const float* v1 = verts1 + (size_t)b*NPTS*3;
    float vx=0.f, vy=0.f, vz=0.f;
    if (n < NPTS){ vx = v1[3*n]; vy = v1[3*n+1]; vz = v1[3*n+2]; }
    float m2x = -2.f*vx, m2y = -2.f*vy, m2z = -2.f*vz;
    float val[10]; int idx[10];
    #pragma unroll
    for (int q = 0; q < 10; q++){ val[q] = 3.4e38f; idx[q] = 0; }
    for (int m0 = 0; m0 < NPTS; m0 += K4CH){
        int cnt = min(K4CH, NPTS - m0);
        __syncthreads();
        for (int i = threadIdx.x; i < cnt; i += K4THREADS){
            float qx = v1[(m0+i)*3], qy = v1[(m0+i)*3+1], qz = v1[(m0+i)*3+2];
            sx[i] = qx; sy[i] = qy; sz[i] = qz;
            sq[i] = fmaf(qx,qx, fmaf(qy,qy, qz*qz));
        }
        if (threadIdx.x < 4){
            sx[cnt+threadIdx.x] = 0.f; sy[cnt+threadIdx.x] = 0.f; sz[cnt+threadIdx.x] = 0.f;
            sq[cnt+threadIdx.x] = 1e30f;
        }
        __syncthreads();
        int ng = (cnt + 3) >> 2;
        for (int g = part; g < ng; g += 4){
            float4 X = *(const float4*)(sx + 4*g);
            float4 Y = *(const float4*)(sy + 4*g);
            float4 Z = *(const float4*)(sz + 4*g);
            float4 Q = *(const float4*)(sq + 4*g);
            float t0 = fmaf(m2x, X.x, Q.x); t0 = fmaf(m2y, Y.x, t0); t0 = fmaf(m2z, Z.x, t0);
            float t1 = fmaf(m2x, X.y, Q.y); t1 = fmaf(m2y, Y.y, t1); t1 = fmaf(m2z, Z.y, t1);
            float t2 = fmaf(m2x, X.z, Q.z); t2 = fmaf(m2y, Y.z, t2); t2 = fmaf(m2z, Z.z, t2);
            float t3 = fmaf(m2x, X.w, Q.w); t3 = fmaf(m2y, Y.w, t3); t3 = fmaf(m2z, Z.w, t3);
            float gm = fminf(fminf(t0,t1), fminf(t2,t3));
            if (gm < val[9]){
                float ds[4]; ds[0]=t0; ds[1]=t1; ds[2]=t2; ds[3]=t3;
                #pragma unroll
                for (int k = 0; k < 4; k++){
                    if (ds[k] < val[9]){
                        float cv = ds[k]; int ci = m0 + 4*g + k;
                        #pragma unroll
                        for (int q = 0; q < 10; q++){
                            if (cv < val[q]){
                                float tv = val[q]; int ti = idx[q];
                                val[q] = cv; idx[q] = ci; cv = tv; ci = ti;
                            }
                        }
                    }
                }
            }
        }
    }
    #pragma unroll
    for (int q = 0; q < 10; q++){ smval[threadIdx.x][q] = val[q]; smidx[threadIdx.x][q] = idx[q]; }
    __syncthreads();
    if (part == 0 && n < NPTS){
        int h0=0,h1=0,h2=0,h3=0;
        int base = threadIdx.x;
        int out = (b*NPTS + n)*KNN;
        #pragma unroll
        for (int q = 0; q < 10; q++){
            float b0 = smval[base][h0],   b1 = smval[base+1][h1];
            float b2 = smval[base+2][h2], b3 = smval[base+3][h3];
            float mm = fminf(fminf(b0,b1), fminf(b2,b3));
            int chosen;
            if (mm == b0){ chosen = smidx[base][h0];   h0++; }
            else if (mm == b1){ chosen = smidx[base+1][h1]; h1++; }
            else if (mm == b2){ chosen = smidx[base+2][h2]; h2++; }
            else { chosen = smidx[base+3][h3]; h3++; }
            g_idx11[out + q] = chosen;
        }
    }
}

// ---------------- K5: deform feature MSE (warp-per-point) ----------------
__global__ void __launch_bounds__(256) k5_deform(const float* __restrict__ feat1){
    int w = threadIdx.x >> 5, lane = threadIdx.x & 31;
    int base = blockIdx.x*64 + w*8;
    float acc = 0.f;
    #pragma unroll
    for (int p = 0; p < 8; p++){
        int bn = base + p;
        if (bn < BATCH*NPTS){
            int b = bn / NPTS, n = bn - b*NPTS;
            const float* f1 = feat1 + (size_t)b*NPTS*CDIM;
            float4 fc = *(const float4*)(f1 + (size_t)n*CDIM + lane*4);
            #pragma unroll
            for (int q = 0; q < KNN; q++){
                int m = g_idx11[bn*KNN + q];
                float4 fm = *(const float4*)(f1 + (size_t)m*CDIM + lane*4);
                float d0 = fm.x - fc.x, d1 = fm.y - fc.y;
                float d2 = fm.z - fc.z, d3 = fm.w - fc.w;
                acc = fmaf(d0,d0, acc); acc = fmaf(d1,d1, acc);
                acc = fmaf(d2,d2, acc); acc = fmaf(d3,d3, acc);
            }
        }
    }
    block_sum_atomic(acc, &g_deform_sum);
}

// ---------------- K_mm: per-(tensor,b) minmax + grid-index minmax ----------------
__global__ void __launch_bounds__(1024) k_mm(const float* __restrict__ verts2){
    __shared__ float rf[32][4];
    __shared__ int ri[32][4];
    __shared__ float bc[4];
    int bx = blockIdx.x;
    int tensor = bx >> 2, b = bx & 3;
    size_t bofs = (size_t)b*NPTS;
    const float* p = tensor ? (verts2 + bofs*3) : (g_verts12 + bofs*3);
    int tid = threadIdx.x, lane = tid & 31, w = tid >> 5;

    float mnx = 1e30f, mny = 1e30f, mxx = -1e30f, mxy = -1e30f;
    for (int i = tid; i < NPTS; i += 1024){
        float x = p[3*i], y = p[3*i+1];
        mnx = fminf(mnx, x); mny = fminf(mny, y);
        mxx = fmaxf(mxx, x); mxy = fmaxf(mxy, y);
    }
    #pragma unroll
    for (int o = 16; o; o >>= 1){
        mnx = fminf(mnx, __shfl_xor_sync(0xffffffffu, mnx, o));
        mny = fminf(mny, __shfl_xor_sync(0xffffffffu, mny, o));
        mxx = fmaxf(mxx, __shfl_xor_sync(0xffffffffu, mxx, o));
        mxy = fmaxf(mxy, __shfl_xor_sync(0xffffffffu, mxy, o));
    }
    if (!lane){ rf[w][0] = mnx; rf[w][1] = mny; rf[w][2] = mxx; rf[w][3] = mxy; }
    __syncthreads();
    if (w == 0){
        mnx = rf[lane][0]; mny = rf[lane][1]; mxx = rf[lane][2]; mxy = rf[lane][3];
        #pragma unroll
        for (int o = 16; o; o >>= 1){
            mnx = fminf(mnx, __shfl_xor_sync(0xffffffffu, mnx, o));
            mny = fminf(mny, __shfl_xor_sync(0xffffffffu, mny, o));
            mxx = fmaxf(mxx, __shfl_xor_sync(0xffffffffu, mxx, o));
            mxy = fmaxf(mxy, __shfl_xor_sync(0xffffffffu, mxy, o));
        }
        if (!lane){
            bc[0] = mnx; bc[1] = mny; bc[2] = mxx; bc[3] = mxy;
            g_mmf[tensor][b][0] = mnx; g_mmf[tensor][b][1] = mny;
            g_mmf[tensor][b][2] = mxx; g_mmf[tensor][b][3] = mxy;
        }
    }
    __syncthreads();
    float minx = bc[0], miny = bc[1], maxx = bc[2], maxy = bc[3];
    float gs = __fdiv_rn(fmaxf(maxx - minx, maxy - miny), 221.0f);

    int imnx = 0x7FFFFFFF, imny = 0x7FFFFFFF;
    int imxx = (int)0x80000000, imxy = (int)0x80000000;
    for (int i = tid; i < NPTS; i += 1024){
        int ix = (int)floorf(__fdiv_rn(p[3*i]   - minx, gs));
        int iy = (int)floorf(__fdiv_rn(p[3*i+1] - miny, gs));
        imnx = min(imnx, ix); imny = min(imny, iy);
        imxx = max(imxx, ix); imxy = max(imxy, iy);
    }
    #pragma unroll
    for (int o = 16; o; o >>= 1){
        imnx = min(imnx, __shfl_xor_sync(0xffffffffu, imnx, o));
        imny = min(imny, __shfl_xor_sync(0xffffffffu, imny, o));
        imxx = max(imxx, __shfl_xor_sync(0xffffffffu, imxx, o));
        imxy = max(imxy, __shfl_xor_sync(0xffffffffu, imxy, o));
    }
    if (!lane){ ri[w][0] = imnx; ri[w][1] = imny; ri[w][2] = imxx; ri[w][3] = imxy; }
    __syncthreads();
    if (w == 0){
        imnx = ri[lane][0]; imny = ri[lane][1]; imxx = ri[lane][2]; imxy = ri[lane][3];
        #pragma unroll
        for (int o = 16; o; o >>= 1){
            imnx = min(imnx, __shfl_xor_sync(0xffffffffu, imnx, o));
            imny = min(imny, __shfl_xor_sync(0xffffffffu, imny, o));
            imxx = max(imxx, __shfl_xor_sync(0xffffffffu, imxx, o));
            imxy = max(imxy, __shfl_xor_sync(0xffffffffu, imxy, o));
        }
        if (!lane){
            g_oxy[tensor][b][0] = 111 - ((imxx + imnx + 2) >> 1);
            g_oxy[tensor][b][1] = 111 - ((imxy + imny + 2) >> 1);
        }
    }
}

// ---------------- K8: scatter z into images ----------------
__global__ void __launch_bounds__(256) k8_scatter(const float* __restrict__ verts2){
    int tb = blockIdx.y;
    int tensor = tb >> 2, b = tb & 3;
    const float* p = tensor ? (verts2 + (size_t)b*NPTS*3) : (g_verts12 + (size_t)b*NPTS*3);
    int i = blockIdx.x*256 + threadIdx.x;
    if (i >= NPTS) return;
    float minx = g_mmf[tensor][b][0];
    float miny = g_mmf[tensor][b][1];
    float maxx = g_mmf[tensor][b][2];
    float maxy = g_mmf[tensor][b][3];
    float gs = __fdiv_rn(fmaxf(maxx - minx, maxy - miny), 221.0f);
    int ix = (int)floorf(__fdiv_rn(p[3*i]   - minx, gs));
    int iy = (int)floorf(__fdiv_rn(p[3*i+1] - miny, gs));
    float z = p[3*i+2];
    int ox = g_oxy[tensor][b][0], oy = g_oxy[tensor][b][1];
    float* img = g_img[tensor] + b*IMGSZ;
    #pragma unroll
    for (int t2 = 0; t2 < 25; t2++){
        int du = t2 / 5;
        int dv = t2 - du*5;
        int uu = ix + du - 1 + ox;
        int vv = iy + dv - 1 + oy;
        uu += (uu < 0) - (uu > IMG-1);
        vv += (vv < 0) - (vv > IMG-1);
        uu = max(0, min(IMG-1, uu));
        vv = max(0, min(IMG-1, vv));
        atomicAdd(&img[uu*IMG + vv], z);
    }
}

// ---------------- K9: image MSE ----------------
__global__ void __launch_bounds__(256) k9_imgloss(){
    int i = blockIdx.x*256 + threadIdx.x;
    float d = 0.f;
    if (i < BATCH*IMGSZ){
        float a = g_img[0][i], b2 = g_img[1][i];
        float s1 = 1.f/(1.f + __expf(-a));
        float s2 = 1.f/(1.f + __expf(-b2));
        float df = s1 - s2;
        d = df*df;
    }
    block_sum_atomic(d, &g_img_sum);
}

// ---------------- K10: finalize ----------------
__global__ void k10_final(float* out){
    if (threadIdx.x == 0 && blockIdx.x == 0){
        double self_l = g_self_sum / (double)(BATCH*NPTS);
        double def_l  = g_deform_sum / ((double)BATCH*NPTS*KNN*CDIM);
        double img_l  = g_img_sum / ((double)BATCH*IMGSZ);
        out[0] = (float)(self_l + img_l + def_l);
    }
}

// ---------------- launch ----------------
extern "C" void kernel_launch(void* const* d_in, const int* in_sizes, int n_in,
                              void* d_out, int out_size){
    const float* verts1 = (const float*)d_in[0];
    const float* verts2 = (const float*)d_in[1];
    const float* feat1  = (const float*)d_in[2];
    const float* feat2  = (const float*)d_in[3];
    float* out = (float*)d_out;

    cudaFuncSetAttribute(k2_softmax_mma, cudaFuncAttributeMaxDynamicSharedMemorySize, K2SMEM);

    k_pre<<<4995, 256>>>(feat1, feat2);
    k2_softmax_mma<<<dim3(MTILES, NSPLIT, BATCH), K2_THREADS, K2SMEM>>>(verts2);
    k3_selfrec<<<dim3((NPTS+63)/64, BATCH), 256>>>(verts2);
    k4_topk<<<dim3((NPTS+K4PTS-1)/K4PTS, BATCH), K4THREADS>>>(verts1);
    k5_deform<<<(BATCH*NPTS + 63)/64, 256>>>(feat1);
    k_mm<<<8, 1024>>>(verts2);
    k8_scatter<<<dim3((NPTS+255)/256, 2*BATCH), 256>>>(verts2);
    k9_imgloss<<<(BATCH*IMGSZ+255)/256, 256>>>();
    k10_final<<<1, 32>>>(out);
}

// round 15
// speedup vs baseline: 1.2857x; 1.1309x over previous
#include <cuda_runtime.h>
#include <cuda_bf16.h>
#include <cstdint>
#include <math.h>

typedef unsigned int u32;
typedef unsigned long long u64;

#define BATCH 4
#define NPTS 4995
#define CDIM 128
#define KNN 10
#define IMG 224
#define IMGSZ (IMG*IMG)

#define MT 128
#define MTILES 40
#define NSPLIT 8
#define CHUNK 640
#define K2_THREADS 512

// K2 smem layout (bytes)
#define BBUF 34816
#define BLO 17408
#define AH_SM 0
#define AL_SM 34816
#define BB_SM 69632
#define CI_SM 208896
#define MG_SM 212992
#define K2SMEM 215552

#define K3CH 2048
#define K4CH 1024
#define K4PTS 32
#define K4THREADS 128
#define QC 12
#define QROW 13

// ---------------- scratch ----------------
__device__ unsigned short g_f1hi[BATCH*NPTS*CDIM];
__device__ unsigned short g_f1lo[BATCH*NPTS*CDIM];
__device__ unsigned short g_f2hi[BATCH*NPTS*CDIM];
__device__ unsigned short g_f2lo[BATCH*NPTS*CDIM];
__device__ float g_nf1[BATCH*NPTS];
__device__ float g_nf2[BATCH*NPTS];
__device__ float g_pm[BATCH*NPTS*NSPLIT];
__device__ float g_ps[BATCH*NPTS*NSPLIT];
__device__ float g_px[BATCH*NPTS*NSPLIT];
__device__ float g_py[BATCH*NPTS*NSPLIT];
__device__ float g_pz[BATCH*NPTS*NSPLIT];
__device__ float g_verts12[BATCH*NPTS*3];
__device__ int   g_idx11[BATCH*NPTS*KNN];
__device__ float g_img[2][BATCH*IMGSZ];
__device__ float g_mmf[2][BATCH][4];
__device__ int   g_oxy[2][BATCH][2];
__device__ double g_self_sum;
__device__ double g_deform_sum;
__device__ double g_img_sum;

// ---------------- generic helpers ----------------
__device__ __forceinline__ unsigned fenc(float f){
    unsigned uu = __float_as_uint(f);
    return (uu & 0x80000000u) ? ~uu : (uu | 0x80000000u);
}
__device__ __forceinline__ float fdec(unsigned uu){
    return __uint_as_float((uu & 0x80000000u) ? (uu ^ 0x80000000u) : ~uu);
}
__device__ __forceinline__ float sqrt_approx(float x){
    float y; asm("sqrt.approx.f32 %0, %1;" : "=f"(y) : "f"(x)); return y;
}
__device__ __forceinline__ void block_sum_atomic(float v, double* target){
    __shared__ float red[32];
    int lane = threadIdx.x & 31, w = threadIdx.x >> 5;
    #pragma unroll
    for (int o = 16; o; o >>= 1) v += __shfl_xor_sync(0xffffffffu, v, o);
    if (!lane) red[w] = v;
    __syncthreads();
    if (w == 0){
        int nw = (blockDim.x + 31) >> 5;
        float s = (lane < nw) ? red[lane] : 0.f;
        #pragma unroll
        for (int o = 16; o; o >>= 1) s += __shfl_xor_sync(0xffffffffu, s, o);
        if (!lane) atomicAdd(target, (double)s);
    }
}
__device__ __forceinline__ u32 smem_u32(const void* p){
    u32 a;
    asm("{ .reg .u64 t; cvta.to.shared.u64 t, %1; cvt.u32.u64 %0, t; }" : "=r"(a) : "l"(p));
    return a;
}
__device__ __forceinline__ void bar_named(int id){
    asm volatile("bar.sync %0, 256;" :: "r"(id) : "memory");
}

// ---------------- mma.sync / ldmatrix wrappers ----------------
__device__ __forceinline__ void ldsm_x4(u32* r, u32 addr){
    asm volatile("ldmatrix.sync.aligned.m8n8.x4.shared.b16 {%0,%1,%2,%3}, [%4];"
        : "=r"(r[0]), "=r"(r[1]), "=r"(r[2]), "=r"(r[3]) : "r"(addr));
}
__device__ __forceinline__ void mma_bf16(float* d, const u32* a, u32 b0, u32 b1){
    asm volatile(
        "mma.sync.aligned.m16n8k16.row.col.f32.bf16.bf16.f32 "
        "{%0,%1,%2,%3}, {%4,%5,%6,%7}, {%8,%9}, {%0,%1,%2,%3};"
        : "+f"(d[0]), "+f"(d[1]), "+f"(d[2]), "+f"(d[3])
        : "r"(a[0]), "r"(a[1]), "r"(a[2]), "r"(a[3]), "r"(b0), "r"(b1));
}

// ---------------- K_pre: init + double-bf16 split + row norms ----------------
__global__ void __launch_bounds__(256) k_pre(const float* __restrict__ f1,
                                             const float* __restrict__ f2){
    int tid = threadIdx.x;
    int i = blockIdx.x*256 + tid;

    if (i < 2*BATCH*IMGSZ) ((float*)g_img)[i] = 0.0f;
    if (i == 0){ g_self_sum = 0.0; g_deform_sum = 0.0; g_img_sum = 0.0; }

    const int half = BATCH*NPTS*CDIM/4;
    if (i < 2*half){
        bool second = i >= half;
        int j = second ? i - half : i;
        float4 v = ((const float4*)(second ? f2 : f1))[j];
        unsigned short* hi = second ? g_f2hi : g_f1hi;
        unsigned short* lo = second ? g_f2lo : g_f1lo;
        float vv[4]; vv[0]=v.x; vv[1]=v.y; vv[2]=v.z; vv[3]=v.w;
        unsigned short hu[4], lu[4];
        #pragma unroll
        for (int c = 0; c < 4; c++){
            __nv_bfloat16 h = __float2bfloat16_rn(vv[c]);
            float r = vv[c] - __bfloat162float(h);
            __nv_bfloat16 l = __float2bfloat16_rn(r);
            hu[c] = __bfloat16_as_ushort(h);
            lu[c] = __bfloat16_as_ushort(l);
        }
        ((uint2*)hi)[j] = make_uint2((u32)hu[0] | ((u32)hu[1] << 16),
                                     (u32)hu[2] | ((u32)hu[3] << 16));
        ((uint2*)lo)[j] = make_uint2((u32)lu[0] | ((u32)lu[1] << 16),
                                     (u32)lu[2] | ((u32)lu[3] << 16));
    }

    int gw = i >> 5;
    int lane = tid & 31;
    if (gw < 2*BATCH*NPTS){
        const float* src; float* dst; int row;
        if (gw < BATCH*NPTS){ src = f1; dst = g_nf1; row = gw; }
        else { src = f2; dst = g_nf2; row = gw - BATCH*NPTS; }
        float4 v = *(const float4*)(src + (size_t)row*CDIM + lane*4);
        float s = v.x*v.x + v.y*v.y + v.z*v.z + v.w*v.w;
        #pragma unroll
        for (int o = 16; o; o >>= 1) s += __shfl_xor_sync(0xffffffffu, s, o);
        if (!lane) dst[row] = s;
    }
}

// ---------------- K2: HMMA fused softmax, two warp-groups pipelined ----------------
__global__ void __launch_bounds__(K2_THREADS)
k2_softmax_mma(const float* __restrict__ verts2){
    extern __shared__ char smem[];
    const int tid = threadIdx.x;
    const int wid = tid >> 5, lane = tid & 31;
    const int grp = wid >> 3;
    const int gwid = wid & 7;
    const int gtid = tid & 255;
    const int b = blockIdx.z, split = blockIdx.y, mt = blockIdx.x;
    const int n0 = mt * MT;
    const int cs = split * CHUNK;
    const int ce = min(cs + CHUNK, NPTS);
    const int T = (ce - cs + 63) >> 6;
    const int H = (T + 1) >> 1;
    const int tbase = grp ? H : 0;
    const int myT = grp ? (T - H) : H;
    const size_t bofs = (size_t)b * NPTS;
    const float* v2 = verts2 + bofs * 3;
    u32 sb = smem_u32(smem);

    for (int i = tid; i < 2048; i += K2_THREADS){
        int row = i >> 4, c8 = i & 15;
        int n = n0 + row;
        uint4 vh = make_uint4(0u,0u,0u,0u);
        uint4 vl = make_uint4(0u,0u,0u,0u);
        if (n < NPTS){
            vh = *(const uint4*)(g_f1hi + ((bofs + n) << 7) + (c8 << 3));
            vl = *(const uint4*)(g_f1lo + ((bofs + n) << 7) + (c8 << 3));
        }
        *(uint4*)(smem + AH_SM + row*272 + c8*16) = vh;
        *(uint4*)(smem + AL_SM + row*272 + c8*16) = vl;
    }
    if (myT > 0){
        int m0 = cs + tbase*64;
        char* bufb = smem + BB_SM + (grp*2 + 0)*BBUF;
        for (int i = gtid; i < 2048; i += 256){
            int row = i >> 5, c8 = i & 31;
            int m = m0 + row;
            uint4 v = make_uint4(0u,0u,0u,0u);
            const unsigned short* src = (c8 < 16) ? g_f2hi : g_f2lo;
            int cc8 = c8 & 15;
            if (m < ce) v = *(const uint4*)(src + ((bofs + m) << 7) + (cc8 << 3));
            *(uint4*)(bufb + ((c8 < 16) ? 0 : BLO) + row*272 + cc8*16) = v;
        }
        if (gtid < 64){
            int m = m0 + gtid;
            float4 ci;
            if (m < ce){ ci.x = g_nf2[bofs+m]; ci.y = v2[m*3]; ci.z = v2[m*3+1]; ci.w = v2[m*3+2]; }
            else { ci.x = 1e30f; ci.y = 0.f; ci.z = 0.f; ci.w = 0.f; }
            *(float4*)(smem + CI_SM + (grp*2 + 0)*1024 + gtid*16) = ci;
        }
    }
    __syncthreads();

    const u32 aRowOff = (u32)((gwid*16 + (lane & 15)) * 272 + (lane >> 4) * 16);
    const u32 aHa = sb + AH_SM + aRowOff;
    const u32 aLa = sb + AL_SM + aRowOff;
    const u32 bOff4 = (u32)(((lane & 7) + ((lane >> 4) << 3)) * 272 + (((lane >> 3) & 1) << 4));

    float nf10 = 0.f, nf11 = 0.f;
    const int r0g = n0 + gwid*16 + (lane >> 2);
    if (r0g < NPTS) nf10 = g_nf1[bofs + r0g];
    if (r0g + 8 < NPTS) nf11 = g_nf1[bofs + r0g + 8];

    float rm0=-1e30f, rs0=0.f, rx0=0.f, ry0=0.f, rz0=0.f;
    float rm1=-1e30f, rs1=0.f, rx1=0.f, ry1=0.f, rz1=0.f;

    for (int j = 0; j < myT; j++){
        if (j + 1 < myT){
            int m0 = cs + (tbase + j + 1)*64;
            int nb = (j + 1) & 1;
            char* bufb = smem + BB_SM + (grp*2 + nb)*BBUF;
            for (int i = gtid; i < 2048; i += 256){
                int row = i >> 5, c8 = i & 31;
                int m = m0 + row;
                uint4 v = make_uint4(0u,0u,0u,0u);
                const unsigned short* src = (c8 < 16) ? g_f2hi : g_f2lo;
                int cc8 = c8 & 15;
                if (m < ce) v = *(const uint4*)(src + ((bofs + m) << 7) + (cc8 << 3));
                *(uint4*)(bufb + ((c8 < 16) ? 0 : BLO) + row*272 + cc8*16) = v;
            }
            if (gtid < 64){
                int m = m0 + gtid;
                float4 ci;
                if (m < ce){ ci.x = g_nf2[bofs+m]; ci.y = v2[m*3]; ci.z = v2[m*3+1]; ci.w = v2[m*3+2]; }
                else { ci.x = 1e30f; ci.y = 0.f; ci.z = 0.f; ci.w = 0.f; }
                *(float4*)(smem + CI_SM + (grp*2 + nb)*1024 + gtid*16) = ci;
            }
        }

        float acc[32];
        #pragma unroll
        for (int i = 0; i < 32; i++) acc[i] = 0.f;
        const u32 bBase = sb + BB_SM + (u32)((grp*2 + (j & 1))*BBUF) + bOff4;
        #pragma unroll
        for (int ks = 0; ks < 8; ks++){
            u32 ah[4], al[4];
            ldsm_x4(ah, aHa + ks*32);
            ldsm_x4(al, aLa + ks*32);
            #pragma unroll
            for (int fp = 0; fp < 4; fp++){
                u32 bh[4], bl[4];
                u32 baddr = bBase + (u32)(fp*4352 + ks*32);
                ldsm_x4(bh, baddr);
                ldsm_x4(bl, baddr + BLO);
                mma_bf16(acc + fp*8,     ah, bh[0], bh[1]);
                mma_bf16(acc + fp*8,     ah, bl[0], bl[1]);
                mma_bf16(acc + fp*8,     al, bh[0], bh[1]);
                mma_bf16(acc + fp*8 + 4, ah, bh[2], bh[3]);
                mma_bf16(acc + fp*8 + 4, ah, bl[2], bl[3]);
                mma_bf16(acc + fp*8 + 4, al, bh[2], bh[3]);
            }
        }

        const char* cib = smem + CI_SM + (grp*2 + (j & 1))*1024;
        float tm0 = -1e30f, tm1 = -1e30f;
        #pragma unroll
        for (int f = 0; f < 8; f++){
            int n = f*8 + (lane & 3)*2;
            float c0x = *(const float*)(cib + n*16);
            float c1x = *(const float*)(cib + n*16 + 16);
            float s0 = fmaxf(fmaf(-2.f, acc[f*4+0], nf10 + c0x), 1e-12f);
            float s1 = fmaxf(fmaf(-2.f, acc[f*4+1], nf10 + c1x), 1e-12f);
            float s2 = fmaxf(fmaf(-2.f, acc[f*4+2], nf11 + c0x), 1e-12f);
            float s3 = fmaxf(fmaf(-2.f, acc[f*4+3], nf11 + c1x), 1e-12f);
            acc[f*4+0] = -100.f*sqrt_approx(s0);
            acc[f*4+1] = -100.f*sqrt_approx(s1);
            acc[f*4+2] = -100.f*sqrt_approx(s2);
            acc[f*4+3] = -100.f*sqrt_approx(s3);
            tm0 = fmaxf(tm0, fmaxf(acc[f*4+0], acc[f*4+1]));
            tm1 = fmaxf(tm1, fmaxf(acc[f*4+2], acc[f*4+3]));
        }
        float nm0 = fmaxf(rm0, tm0), nm1 = fmaxf(rm1, tm1);
        float sc0 = __expf(rm0 - nm0), sc1 = __expf(rm1 - nm1);
        rs0 *= sc0; rx0 *= sc0; ry0 *= sc0; rz0 *= sc0; rm0 = nm0;
        rs1 *= sc1; rx1 *= sc1; ry1 *= sc1; rz1 *= sc1; rm1 = nm1;
        #pragma unroll
        for (int f = 0; f < 8; f++){
            int n = f*8 + (lane & 3)*2;
            float4 c0 = *(const float4*)(cib + n*16);
            float4 c1 = *(const float4*)(cib + n*16 + 16);
            float w0 = __expf(acc[f*4+0] - nm0);
            float w1 = __expf(acc[f*4+1] - nm0);
            float w2 = __expf(acc[f*4+2] - nm1);
            float w3 = __expf(acc[f*4+3] - nm1);
            rs0 += w0 + w1; rs1 += w2 + w3;
            rx0 = fmaf(w0, c0.y, fmaf(w1, c1.y, rx0));
            ry0 = fmaf(w0, c0.z, fmaf(w1, c1.z, ry0));
            rz0 = fmaf(w0, c0.w, fmaf(w1, c1.w, rz0));
            rx1 = fmaf(w2, c0.y, fmaf(w3, c1.y, rx1));
            ry1 = fmaf(w2, c0.z, fmaf(w3, c1.z, ry1));
            rz1 = fmaf(w2, c0.w, fmaf(w3, c1.w, rz1));
        }
        bar_named(1 + grp);
    }

    #pragma unroll
    for (int o = 1; o <= 2; o <<= 1){
        float om = __shfl_xor_sync(0xffffffffu, rm0, o);
        float os = __shfl_xor_sync(0xffffffffu, rs0, o);
        float ox = __shfl_xor_sync(0xffffffffu, rx0, o);
        float oy = __shfl_xor_sync(0xffffffffu, ry0, o);
        float oz = __shfl_xor_sync(0xffffffffu, rz0, o);
        float nm = fmaxf(rm0, om);
        float e1 = __expf(rm0 - nm), e2 = __expf(om - nm);
        rs0 = rs0*e1 + os*e2; rx0 = rx0*e1 + ox*e2;
        ry0 = ry0*e1 + oy*e2; rz0 = rz0*e1 + oz*e2; rm0 = nm;
        om = __shfl_xor_sync(0xffffffffu, rm1, o);
        os = __shfl_xor_sync(0xffffffffu, rs1, o);
        ox = __shfl_xor_sync(0xffffffffu, rx1, o);
        oy = __shfl_xor_sync(0xffffffffu, ry1, o);
        oz = __shfl_xor_sync(0xffffffffu, rz1, o);
        nm = fmaxf(rm1, om);
        e1 = __expf(rm1 - nm); e2 = __expf(om - nm);
        rs1 = rs1*e1 + os*e2; rx1 = rx1*e1 + ox*e2;
        ry1 = ry1*e1 + oy*e2; rz1 = rz1*e1 + oz*e2; rm1 = nm;
    }

    __syncthreads();
    float* mg = (float*)(smem + MG_SM);
    int rl0 = gwid*16 + (lane >> 2);
    if (grp == 1 && (lane & 3) == 0){
        mg[rl0*5+0] = rm0; mg[rl0*5+1] = rs0; mg[rl0*5+2] = rx0; mg[rl0*5+3] = ry0; mg[rl0*5+4] = rz0;
        mg[(rl0+8)*5+0] = rm1; mg[(rl0+8)*5+1] = rs1; mg[(rl0+8)*5+2] = rx1; mg[(rl0+8)*5+3] = ry1; mg[(rl0+8)*5+4] = rz1;
    }
    __syncthreads();
    if (grp == 0 && (lane & 3) == 0){
        float m2 = mg[rl0*5+0], s2 = mg[rl0*5+1], x2 = mg[rl0*5+2], y2 = mg[rl0*5+3], z2 = mg[rl0*5+4];
        float nm = fmaxf(rm0, m2);
        float e1 = __expf(rm0 - nm), e2 = __expf(m2 - nm);
        float S = rs0*e1 + s2*e2, X = rx0*e1 + x2*e2, Y = ry0*e1 + y2*e2, Z = rz0*e1 + z2*e2;
        int n = n0 + rl0;
        if (n < NPTS){
            size_t pi = (bofs + n)*NSPLIT + split;
            g_pm[pi] = nm; g_ps[pi] = S; g_px[pi] = X; g_py[pi] = Y; g_pz[pi] = Z;
        }
        m2 = mg[(rl0+8)*5+0]; s2 = mg[(rl0+8)*5+1]; x2 = mg[(rl0+8)*5+2]; y2 = mg[(rl0+8)*5+3]; z2 = mg[(rl0+8)*5+4];
        nm = fmaxf(rm1, m2);
        e1 = __expf(rm1 - nm); e2 = __expf(m2 - nm);
        S = rs1*e1 + s2*e2; X = rx1*e1 + x2*e2; Y = ry1*e1 + y2*e2; Z = rz1*e1 + z2*e2;
        n = n0 + rl0 + 8;
        if (n < NPTS){
            size_t pi = (bofs + n)*NSPLIT + split;
            g_pm[pi] = nm; g_ps[pi] = S; g_px[pi] = X; g_py[pi] = Y; g_pz[pi] = Z;
        }
    }
}

// ---------------- K3: split-merge + self_rec (expansion form) ----------------
__global__ void __launch_bounds__(256) k3_selfrec(const float* __restrict__ verts2){
    __shared__ __align__(16) float sx[K3CH+4];
    __shared__ __align__(16) float sy[K3CH+4];
    __shared__ __align__(16) float sz[K3CH+4];
    __shared__ __align__(16) float sq[K3CH+4];
    int b = blockIdx.y;
    int part = threadIdx.x & 3;
    int nl = threadIdx.x >> 2;
    int n = blockIdx.x*64 + nl;
    bool valid = n < NPTS;
    size_t bofs = (size_t)b*NPTS;
    float vx=0.f, vy=0.f, vz=0.f;
    if (valid){
        float m = -1e30f, s = 0.f, x = 0.f, y = 0.f, z = 0.f;
        #pragma unroll
        for (int sp = 0; sp < NSPLIT; sp++){
            size_t pi = (bofs + n)*NSPLIT + sp;
            float m2 = g_pm[pi], s2 = g_ps[pi], x2 = g_px[pi], y2 = g_py[pi], z2 = g_pz[pi];
            float nm = fmaxf(m, m2);
            float a1 = __expf(m - nm), a2 = __expf(m2 - nm);
            s = s*a1 + s2*a2; x = x*a1 + x2*a2; y = y*a1 + y2*a2; z = z*a1 + z2*a2;
            m = nm;
        }
        float inv = 1.f / s;
        vx = x*inv; vy = y*inv; vz = z*inv;
        if (part == 0){
            g_verts12[(bofs + n)*3 + 0] = vx;
            g_verts12[(bofs + n)*3 + 1] = vy;
            g_verts12[(bofs + n)*3 + 2] = vz;
        }
    }
    float np = fmaf(vx,vx, fmaf(vy,vy, vz*vz));
    float m2x = -2.f*vx, m2y = -2.f*vy, m2z = -2.f*vz;
    const float* v2 = verts2 + bofs*3;
    float best = 3.4e38f;
    for (int m0 = 0; m0 < NPTS; m0 += K3CH){
        int cnt = min(K3CH, NPTS - m0);
        __syncthreads();
        for (int i = threadIdx.x; i < cnt; i += 256){
            float qx = v2[(m0+i)*3], qy = v2[(m0+i)*3+1], qz = v2[(m0+i)*3+2];
            sx[i] = qx; sy[i] = qy; sz[i] = qz;
            sq[i] = fmaf(qx,qx, fmaf(qy,qy, qz*qz));
        }
        if (threadIdx.x < 4){
            sx[cnt+threadIdx.x] = 0.f; sy[cnt+threadIdx.x] = 0.f; sz[cnt+threadIdx.x] = 0.f;
            sq[cnt+threadIdx.x] = 1e30f;
        }
        __syncthreads();
        int ng = (cnt + 3) >> 2;
        for (int g = part; g < ng; g += 4){
            float4 X = *(const float4*)(sx + 4*g);
            float4 Y = *(const float4*)(sy + 4*g);
            float4 Z = *(const float4*)(sz + 4*g);
            float4 Q = *(const float4*)(sq + 4*g);
            float t0 = fmaf(m2x, X.x, Q.x); t0 = fmaf(m2y, Y.x, t0); t0 = fmaf(m2z, Z.x, t0);
            float t1 = fmaf(m2x, X.y, Q.y); t1 = fmaf(m2y, Y.y, t1); t1 = fmaf(m2z, Z.y, t1);
            float t2 = fmaf(m2x, X.z, Q.z); t2 = fmaf(m2y, Y.z, t2); t2 = fmaf(m2z, Z.z, t2);
            float t3 = fmaf(m2x, X.w, Q.w); t3 = fmaf(m2y, Y.w, t3); t3 = fmaf(m2z, Z.w, t3);
            best = fminf(best, fminf(fminf(t0,t1), fminf(t2,t3)));
        }
    }
    best = fminf(best, __shfl_xor_sync(0xffffffffu, best, 1));
    best = fminf(best, __shfl_xor_sync(0xffffffffu, best, 2));
    float contrib = (part == 0 && valid) ? (best + np) : 0.f;
    __syncthreads();
    block_sum_atomic(contrib, &g_self_sum);
}

// ---------------- K4: top-10 NN, deferred-insert queue (fenc-ordered keys) ----------------
__global__ void __launch_bounds__(K4THREADS) k4_topk(const float* __restrict__ verts1){
    __shared__ __align__(16) float sx[K4CH+4];
    __shared__ __align__(16) float sy[K4CH+4];
    __shared__ __align__(16) float sz[K4CH+4];
    __shared__ __align__(16) float sq[K4CH+4];
    __shared__ u64 qbuf[K4THREADS][QROW];
    const int tid = threadIdx.x;
    int b = blockIdx.y;
    int part = tid & 3;
    int nl = tid >> 2;
    int n = blockIdx.x*K4PTS + nl;
    const float* v1 = verts1 + (size_t)b*NPTS*3;
    float vx=0.f, vy=0.f, vz=0.f;
    if (n < NPTS){ vx = v1[3*n]; vy = v1[3*n+1]; vz = v1[3*n+2]; }
    float m2x = -2.f*vx, m2y = -2.f*vy, m2z = -2.f*vz;
    u64 key[10];
    const u64 KINIT = ((u64)fenc(3.4e38f) << 32) | 0xFFFFFFFFull;
    #pragma unroll
    for (int q = 0; q < 10; q++) key[q] = KINIT;
    float v9 = 3.4e38f;
    int cnt = 0;

    for (int m0 = 0; m0 < NPTS; m0 += K4CH){
        int cc = min(K4CH, NPTS - m0);
        __syncthreads();
        for (int i = tid; i < cc; i += K4THREADS){
            float qx = v1[(m0+i)*3], qy = v1[(m0+i)*3+1], qz = v1[(m0+i)*3+2];
            sx[i] = qx; sy[i] = qy; sz[i] = qz;
            sq[i] = fmaf(qx,qx, fmaf(qy,qy, qz*qz));
        }
        if (tid < 4){
            sx[cc+tid] = 0.f; sy[cc+tid] = 0.f; sz[cc+tid] = 0.f;
            sq[cc+tid] = 1e30f;
        }
        __syncthreads();
        int ng = (cc + 3) >> 2;
        int ngu = (ng + 3) >> 2;
        for (int gb = 0; gb < ngu; gb++){
            int g = part + gb*4;
            if (g < ng){
                float4 X = *(const float4*)(sx + 4*g);
                float4 Y = *(const float4*)(sy + 4*g);
                float4 Z = *(const float4*)(sz + 4*g);
                float4 Q = *(const float4*)(sq + 4*g);
                float t0 = fmaf(m2x, X.x, Q.x); t0 = fmaf(m2y, Y.x, t0); t0 = fmaf(m2z, Z.x, t0);
                float t1 = fmaf(m2x, X.y, Q.y); t1 = fmaf(m2y, Y.y, t1); t1 = fmaf(m2z, Z.y, t1);
                float t2 = fmaf(m2x, X.z, Q.z); t2 = fmaf(m2y, Y.z, t2); t2 = fmaf(m2z, Z.z, t2);
                float t3 = fmaf(m2x, X.w, Q.w); t3 = fmaf(m2y, Y.w, t3); t3 = fmaf(m2z, Z.w, t3);
                float gm = fminf(fminf(t0,t1), fminf(t2,t3));
                if (gm < v9){
                    int base = m0 + 4*g;
                    if (t0 < v9) qbuf[tid][cnt++] = ((u64)fenc(t0) << 32) | (u32)(base);
                    if (t1 < v9) qbuf[tid][cnt++] = ((u64)fenc(t1) << 32) | (u32)(base+1);
                    if (t2 < v9) qbuf[tid][cnt++] = ((u64)fenc(t2) << 32) | (u32)(base+2);
                    if (t3 < v9) qbuf[tid][cnt++] = ((u64)fenc(t3) << 32) | (u32)(base+3);
                }
            }
            if (__any_sync(0xffffffffu, cnt >= QC-4)){
                int mc = __reduce_max_sync(0xffffffffu, cnt);
                for (int it = 0; it < mc; it++){
                    if (it < cnt){
                        u64 k = qbuf[tid][it];
                        #pragma unroll
                        for (int q = 0; q < 10; q++){
                            if (k < key[q]){ u64 t = key[q]; key[q] = k; k = t; }
                        }
                    }
                }
                cnt = 0;
                v9 = fdec((u32)(key[9] >> 32));
            }
        }
    }
    {
        int mc = __reduce_max_sync(0xffffffffu, cnt);
        for (int it = 0; it < mc; it++){
            if (it < cnt){
                u64 k = qbuf[tid][it];
                #pragma unroll
                for (int q = 0; q < 10; q++){
                    if (k < key[q]){ u64 t = key[q]; key[q] = k; k = t; }
                }
            }
        }
    }
    #pragma unroll
    for (int q = 0; q < 10; q++) qbuf[tid][q] = key[q];
    __syncthreads();
    if (part == 0 && n < NPTS){
        int h0=0,h1=0,h2=0,h3=0;
        int base = tid;
        int out = (b*NPTS + n)*KNN;
        #pragma unroll
        for (int q = 0; q < 10; q++){
            u64 b0 = qbuf[base][h0],   b1 = qbuf[base+1][h1];
            u64 b2 = qbuf[base+2][h2], b3 = qbuf[base+3][h3];
            u64 m01 = (b0 <= b1) ? b0 : b1;
            u64 m23 = (b2 <= b3) ? b2 : b3;
            u64 mm = (m01 <= m23) ? m01 : m23;
            if (mm == b0) h0++;
            else if (mm == b1) h1++;
            else if (mm == b2) h2++;
            else h3++;
            g_idx11[out + q] = (int)(mm & 0xFFFFFFFFull);
        }
    }
}

// ---------------- K5: deform feature MSE (warp-per-point) ----------------
__global__ void __launch_bounds__(256) k5_deform(const float* __restrict__ feat1){
    int w = threadIdx.x >> 5, lane = threadIdx.x & 31;
    int base = blockIdx.x*64 + w*8;
    float acc = 0.f;
    #pragma unroll
    for (int p = 0; p < 8; p++){
        int bn = base + p;
        if (bn < BATCH*NPTS){
            int b = bn / NPTS, n = bn - b*NPTS;
            const float* f1 = feat1 + (size_t)b*NPTS*CDIM;
            float4 fc = *(const float4*)(f1 + (size_t)n*CDIM + lane*4);
            #pragma unroll
            for (int q = 0; q < KNN; q++){
                int m = g_idx11[bn*KNN + q];
                float4 fm = *(const float4*)(f1 + (size_t)m*CDIM + lane*4);
                float d0 = fm.x - fc.x, d1 = fm.y - fc.y;
                float d2 = fm.z - fc.z, d3 = fm.w - fc.w;
                acc = fmaf(d0,d0, acc); acc = fmaf(d1,d1, acc);
                acc = fmaf(d2,d2, acc); acc = fmaf(d3,d3, acc);
            }
        }
    }
    block_sum_atomic(acc, &g_deform_sum);
}

// ---------------- K_mm: per-(tensor,b) minmax + grid-index minmax ----------------
__global__ void __launch_bounds__(1024) k_mm(const float* __restrict__ verts2){
    __shared__ float rf[32][4];
    __shared__ int ri[32][4];
    __shared__ float bc[4];
    int bx = blockIdx.x;
    int tensor = bx >> 2, b = bx & 3;
    size_t bofs = (size_t)b*NPTS;
    const float* p = tensor ? (verts2 + bofs*3) : (g_verts12 + bofs*3);
    int tid = threadIdx.x, lane = tid & 31, w = tid >> 5;

    float mnx = 1e30f, mny = 1e30f, mxx = -1e30f, mxy = -1e30f;
    for (int i = tid; i < NPTS; i += 1024){
        float x = p[3*i], y = p[3*i+1];
        mnx = fminf(mnx, x); mny = fminf(mny, y);
        mxx = fmaxf(mxx, x); mxy = fmaxf(mxy, y);
    }
    #pragma unroll
    for (int o = 16; o; o >>= 1){
        mnx = fminf(mnx, __shfl_xor_sync(0xffffffffu, mnx, o));
        mny = fminf(mny, __shfl_xor_sync(0xffffffffu, mny, o));
        mxx = fmaxf(mxx, __shfl_xor_sync(0xffffffffu, mxx, o));
        mxy = fmaxf(mxy, __shfl_xor_sync(0xffffffffu, mxy, o));
    }
    if (!lane){ rf[w][0] = mnx; rf[w][1] = mny; rf[w][2] = mxx; rf[w][3] = mxy; }
    __syncthreads();
    if (w == 0){
        mnx = rf[lane][0]; mny = rf[lane][1]; mxx = rf[lane][2]; mxy = rf[lane][3];
        #pragma unroll
        for (int o = 16; o; o >>= 1){
            mnx = fminf(mnx, __shfl_xor_sync(0xffffffffu, mnx, o));
            mny = fminf(mny, __shfl_xor_sync(0xffffffffu, mny, o));
            mxx = fmaxf(mxx, __shfl_xor_sync(0xffffffffu, mxx, o));
            mxy = fmaxf(mxy, __shfl_xor_sync(0xffffffffu, mxy, o));
        }
        if (!lane){
            bc[0] = mnx; bc[1] = mny; bc[2] = mxx; bc[3] = mxy;
            g_mmf[tensor][b][0] = mnx; g_mmf[tensor][b][1] = mny;
            g_mmf[tensor][b][2] = mxx; g_mmf[tensor][b][3] = mxy;
        }
    }
    __syncthreads();
    float minx = bc[0], miny = bc[1], maxx = bc[2], maxy = bc[3];
    float gs = __fdiv_rn(fmaxf(maxx - minx, maxy - miny), 221.0f);

    int imnx = 0x7FFFFFFF, imny = 0x7FFFFFFF;
    int imxx = (int)0x80000000, imxy = (int)0x80000000;
    for (int i = tid; i < NPTS; i += 1024){
        int ix = (int)floorf(__fdiv_rn(p[3*i]   - minx, gs));
        int iy = (int)floorf(__fdiv_rn(p[3*i+1] - miny, gs));
        imnx = min(imnx, ix); imny = min(imny, iy);
        imxx = max(imxx, ix); imxy = max(imxy, iy);
    }
    #pragma unroll
    for (int o = 16; o; o >>= 1){
        imnx = min(imnx, __shfl_xor_sync(0xffffffffu, imnx, o));
        imny = min(imny, __shfl_xor_sync(0xffffffffu, imny, o));
        imxx = max(imxx, __shfl_xor_sync(0xffffffffu, imxx, o));
        imxy = max(imxy, __shfl_xor_sync(0xffffffffu, imxy, o));
    }
    if (!lane){ ri[w][0] = imnx; ri[w][1] = imny; ri[w][2] = imxx; ri[w][3] = imxy; }
    __syncthreads();
    if (w == 0){
        imnx = ri[lane][0]; imny = ri[lane][1]; imxx = ri[lane][2]; imxy = ri[lane][3];
        #pragma unroll
        for (int o = 16; o; o >>= 1){
            imnx = min(imnx, __shfl_xor_sync(0xffffffffu, imnx, o));
            imny = min(imny, __shfl_xor_sync(0xffffffffu, imny, o));
            imxx = max(imxx, __shfl_xor_sync(0xffffffffu, imxx, o));
            imxy = max(imxy, __shfl_xor_sync(0xffffffffu, imxy, o));
        }
        if (!lane){
            g_oxy[tensor][b][0] = 111 - ((imxx + imnx + 2) >> 1);
            g_oxy[tensor][b][1] = 111 - ((imxy + imny + 2) >> 1);
        }
    }
}

// ---------------- K8: scatter z into images ----------------
__global__ void __launch_bounds__(256) k8_scatter(const float* __restrict__ verts2){
    int tb = blockIdx.y;
    int tensor = tb >> 2, b = tb & 3;
    const float* p = tensor ? (verts2 + (size_t)b*NPTS*3) : (g_verts12 + (size_t)b*NPTS*3);
    int i = blockIdx.x*256 + threadIdx.x;
    if (i >= NPTS) return;
    float minx = g_mmf[tensor][b][0];
    float miny = g_mmf[tensor][b][1];
    float maxx = g_mmf[tensor][b][2];
    float maxy = g_mmf[tensor][b][3];
    float gs = __fdiv_rn(fmaxf(maxx - minx, maxy - miny), 221.0f);
    int ix = (int)floorf(__fdiv_rn(p[3*i]   - minx, gs));
    int iy = (int)floorf(__fdiv_rn(p[3*i+1] - miny, gs));
    float z = p[3*i+2];
    int ox = g_oxy[tensor][b][0], oy = g_oxy[tensor][b][1];
    float* img = g_img[tensor] + b*IMGSZ;
    #pragma unroll
    for (int t2 = 0; t2 < 25; t2++){
        int du = t2 / 5;
        int dv = t2 - du*5;
        int uu = ix + du - 1 + ox;
        int vv = iy + dv - 1 + oy;
        uu += (uu < 0) - (uu > IMG-1);
        vv += (vv < 0) - (vv > IMG-1);
        uu = max(0, min(IMG-1, uu));
        vv = max(0, min(IMG-1, vv));
        atomicAdd(&img[uu*IMG + vv], z);
    }
}

// ---------------- K9: image MSE ----------------
__global__ void __launch_bounds__(256) k9_imgloss(){
    int i = blockIdx.x*256 + threadIdx.x;
    float d = 0.f;
    if (i < BATCH*IMGSZ){
        float a = g_img[0][i], b2 = g_img[1][i];
        float s1 = 1.f/(1.f + __expf(-a));
        float s2 = 1.f/(1.f + __expf(-b2));
        float df = s1 - s2;
        d = df*df;
    }
    block_sum_atomic(d, &g_img_sum);
}

// ---------------- K10: finalize ----------------
__global__ void k10_final(float* out){
    if (threadIdx.x == 0 && blockIdx.x == 0){
        double self_l = g_self_sum / (double)(BATCH*NPTS);
        double def_l  = g_deform_sum / ((double)BATCH*NPTS*KNN*CDIM);
        double img_l  = g_img_sum / ((double)BATCH*IMGSZ);
        out[0] = (float)(self_l + img_l + def_l);
    }
}

// ---------------- launch ----------------
extern "C" void kernel_launch(void* const* d_in, const int* in_sizes, int n_in,
                              void* d_out, int out_size){
    const float* verts1 = (const float*)d_in[0];
    const float* verts2 = (const float*)d_in[1];
    const float* feat1  = (const float*)d_in[2];
    const float* feat2  = (const float*)d_in[3];
    float* out = (float*)d_out;

    cudaFuncSetAttribute(k2_softmax_mma, cudaFuncAttributeMaxDynamicSharedMemorySize, K2SMEM);

    k_pre<<<4995, 256>>>(feat1, feat2);
    k2_softmax_mma<<<dim3(MTILES, NSPLIT, BATCH), K2_THREADS, K2SMEM>>>(verts2);
    k3_selfrec<<<dim3((NPTS+63)/64, BATCH), 256>>>(verts2);
    k4_topk<<<dim3((NPTS+K4PTS-1)/K4PTS, BATCH), K4THREADS>>>(verts1);
    k5_deform<<<(BATCH*NPTS + 63)/64, 256>>>(feat1);
    k_mm<<<8, 1024>>>(verts2);
    k8_scatter<<<dim3((NPTS+255)/256, 2*BATCH), 256>>>(verts2);
    k9_imgloss<<<(BATCH*IMGSZ+255)/256, 256>>>();
    k10_final<<<1, 32>>>(out);
}